// round 10
// baseline (speedup 1.0000x reference)
#include <cuda_runtime.h>
#include <math.h>
#include <stdint.h>

#define NN 16384
#define EE 131072
#define BB 16
#define HH 2
#define MAXD 512
#define MAXHD 1024
#define OUTC 896

#define AS_STAGE 2560
#define BS_STAGE 2176
#define SMEM_FLOATS (3 * (AS_STAGE + BS_STAGE))
#define SMEM_BYTES (SMEM_FLOATS * 4)

// ---------------- scratch (device globals; no allocation) ----------------
__device__ float g_x[(size_t)NN * MAXHD];
__device__ float g_y[(size_t)NN * MAXHD];
__device__ float g_h[(size_t)NN * MAXHD];
__device__ float g_r[(size_t)NN * MAXHD];
__device__ float g_el[NN * HH];
__device__ float g_er[NN * HH];
__device__ int   g_indptr[NN + 1];
__device__ int   g_cnt[NN];
__device__ int   g_cur[NN];
__device__ int   g_esrc[EE];
__device__ int   g_bsum[64];
__device__ int   g_boff[64];
__device__ float g_s1[MAXD];
__device__ float g_s2[MAXD];
__device__ float g_scale[MAXD];
__device__ float g_bias[MAXD];
__device__ float g_parts[BB * OUTC];
__device__ int   g_counts[BB];

__device__ __forceinline__ float lrelu(float v, float s) { return v > 0.f ? v : s * v; }

__device__ __forceinline__ void cp_async16(uint32_t saddr, const void* gptr) {
    asm volatile("cp.async.cg.shared.global [%0], [%1], 16;" :: "r"(saddr), "l"(gptr));
}
__device__ __forceinline__ void cp_commit() { asm volatile("cp.async.commit_group;"); }

// ---------------- front ----------------
__global__ void k_zero() {
    int i = blockIdx.x * blockDim.x + threadIdx.x;
    if (i < BB * OUTC) g_parts[i] = 0.f;
    if (i < BB) g_counts[i] = 0;
    if (i < NN) g_cnt[i] = 0;
}

__global__ void k_build(const int* __restrict__ dst, const int* __restrict__ gid) {
    int i = blockIdx.x * blockDim.x + threadIdx.x;
    if (i < EE) atomicAdd(&g_cnt[dst[i]], 1);
    if (i < NN) atomicAdd(&g_counts[gid[i]], 1);
}

__global__ void k_scan1() {
    __shared__ int sm[256];
    int tid = threadIdx.x;
    int i = blockIdx.x * 256 + tid;
    int v = g_cnt[i];
    sm[tid] = v;
    __syncthreads();
    for (int off = 1; off < 256; off <<= 1) {
        int t = (tid >= off) ? sm[tid - off] : 0;
        __syncthreads();
        sm[tid] += t;
        __syncthreads();
    }
    g_indptr[i] = sm[tid] - v;
    g_cur[i] = 0;
    if (tid == 255) g_bsum[blockIdx.x] = sm[255];
}

__global__ void k_scan2() {
    __shared__ int sm[64];
    int tid = threadIdx.x;
    int v = g_bsum[tid];
    sm[tid] = v;
    __syncthreads();
    for (int off = 1; off < 64; off <<= 1) {
        int t = (tid >= off) ? sm[tid - off] : 0;
        __syncthreads();
        sm[tid] += t;
        __syncthreads();
    }
    g_boff[tid] = sm[tid] - v;
    if (tid == 63) g_indptr[NN] = sm[63];
}

__global__ void k_scan3() {
    int i = blockIdx.x * blockDim.x + threadIdx.x;
    if (i < NN) g_indptr[i] += g_boff[i >> 8];
}

__global__ void k_scatter(const int* __restrict__ src, const int* __restrict__ dst) {
    int i = blockIdx.x * blockDim.x + threadIdx.x;
    if (i < EE) {
        int d = dst[i];
        int p = g_indptr[d] + atomicAdd(&g_cur[d], 1);
        g_esrc[p] = src[i];
    }
}

// ---------------- TF32 tensor-core GEMM, cp.async 3-stage pipelined ----------------
__global__ void __launch_bounds__(256) k_mma(const float* __restrict__ Aext, int use_ext,
                                             const float* __restrict__ Bw,
                                             const float* __restrict__ Br,
                                             int K, int Nc) {
    extern __shared__ float smem[];
    float* AsBase = smem;
    float* BsBase = smem + 3 * AS_STAGE;

    const float* A = use_ext ? Aext : g_y;
    const float* B = blockIdx.z ? Br : Bw;
    float* C = blockIdx.z ? g_r : g_h;

    int tid = threadIdx.x;
    int lane = tid & 31;
    int warp = tid >> 5;
    int wm = (warp >> 1) * 32;
    int wn = (warp & 1) * 64;
    int rowT = blockIdx.y * 128;
    int colT = blockIdx.x * 128;
    int gr = lane >> 2;
    int tg = lane & 3;

    int aRow = tid >> 2;
    int aCol = (tid & 3) * 4;
    int bRow = tid >> 5;
    int bCol = (tid & 31) * 4;

    float acc[2][8][4];
#pragma unroll
    for (int i = 0; i < 2; i++)
#pragma unroll
        for (int j = 0; j < 8; j++)
#pragma unroll
            for (int c = 0; c < 4; c++) acc[i][j][c] = 0.f;

    int iters = K >> 4;

    auto load_stage = [&](int s, int kt) {
        float* As = AsBase + s * AS_STAGE;
        float* Bs = BsBase + s * BS_STAGE;
#pragma unroll
        for (int p = 0; p < 2; p++) {
            int r = aRow + p * 64;
            uint32_t sa = (uint32_t)__cvta_generic_to_shared(&As[r * 20 + aCol]);
            cp_async16(sa, A + (size_t)(rowT + r) * K + kt + aCol);
        }
#pragma unroll
        for (int p = 0; p < 2; p++) {
            int r = bRow + p * 8;
            uint32_t sa = (uint32_t)__cvta_generic_to_shared(&Bs[r * 136 + bCol]);
            cp_async16(sa, B + (size_t)(kt + r) * Nc + colT + bCol);
        }
    };

    load_stage(0, 0);
    cp_commit();
    load_stage(1, 16);
    cp_commit();

    for (int it = 0; it < iters; it++) {
        if (it + 1 < iters) asm volatile("cp.async.wait_group 1;");
        else                asm volatile("cp.async.wait_group 0;");
        __syncthreads();

        if (it + 2 < iters) {
            load_stage((it + 2) % 3, (it + 2) << 4);
            cp_commit();
        }

        int cur = it % 3;
        const float* As = AsBase + cur * AS_STAGE;
        const float* Bs = BsBase + cur * BS_STAGE;
#pragma unroll
        for (int kk = 0; kk < 16; kk += 8) {
            float af[2][4];
#pragma unroll
            for (int i = 0; i < 2; i++) {
                int m0 = wm + i * 16 + gr;
                af[i][0] = As[m0 * 20 + kk + tg];
                af[i][1] = As[(m0 + 8) * 20 + kk + tg];
                af[i][2] = As[m0 * 20 + kk + tg + 4];
                af[i][3] = As[(m0 + 8) * 20 + kk + tg + 4];
            }
            float bf[8][2];
#pragma unroll
            for (int j = 0; j < 8; j++) {
                int n0 = wn + j * 8 + gr;
                bf[j][0] = Bs[(kk + tg) * 136 + n0];
                bf[j][1] = Bs[(kk + tg + 4) * 136 + n0];
            }
#pragma unroll
            for (int i = 0; i < 2; i++)
#pragma unroll
                for (int j = 0; j < 8; j++) {
                    asm volatile(
                        "mma.sync.aligned.m16n8k8.row.col.f32.tf32.tf32.f32 "
                        "{%0,%1,%2,%3},{%4,%5,%6,%7},{%8,%9},{%0,%1,%2,%3};"
                        : "+f"(acc[i][j][0]), "+f"(acc[i][j][1]),
                          "+f"(acc[i][j][2]), "+f"(acc[i][j][3])
                        : "r"(__float_as_uint(af[i][0])), "r"(__float_as_uint(af[i][1])),
                          "r"(__float_as_uint(af[i][2])), "r"(__float_as_uint(af[i][3])),
                          "r"(__float_as_uint(bf[j][0])), "r"(__float_as_uint(bf[j][1])));
                }
        }
        __syncthreads();
    }

#pragma unroll
    for (int i = 0; i < 2; i++) {
        int r0 = rowT + wm + i * 16 + gr;
#pragma unroll
        for (int j = 0; j < 8; j++) {
            int ccol = colT + wn + j * 8 + tg * 2;
            *reinterpret_cast<float2*>(C + (size_t)r0 * Nc + ccol) =
                make_float2(acc[i][j][0], acc[i][j][1]);
            *reinterpret_cast<float2*>(C + (size_t)(r0 + 8) * Nc + ccol) =
                make_float2(acc[i][j][2], acc[i][j][3]);
        }
    }
}

// ---------------- attention projections el/er (+ zero s1/s2, FULL range) ----------------
__global__ void k_attn(const float* __restrict__ al, const float* __restrict__ ar, int d) {
    if (blockIdx.x == 0) {
        g_s1[threadIdx.x] = 0.f;
        g_s1[threadIdx.x + 256] = 0.f;
        g_s2[threadIdx.x] = 0.f;
        g_s2[threadIdx.x + 256] = 0.f;
    }
    int gw = (blockIdx.x * blockDim.x + threadIdx.x) >> 5;
    int lane = threadIdx.x & 31;
    if (gw >= NN * HH) return;
    int n = gw >> 1, hd = gw & 1;
    const float4* hr = (const float4*)(g_h + (size_t)n * (2 * d) + hd * d);
    const float4* av = (const float4*)(al + hd * d);
    const float4* bv = (const float4*)(ar + hd * d);
    int q = d >> 2;
    float sl = 0.f, sr = 0.f;
    for (int c = lane; c < q; c += 32) {
        float4 v = hr[c], a = av[c], b = bv[c];
        sl += v.x * a.x + v.y * a.y + v.z * a.z + v.w * a.w;
        sr += v.x * b.x + v.y * b.y + v.z * b.z + v.w * b.w;
    }
#pragma unroll
    for (int o = 16; o > 0; o >>= 1) {
        sl += __shfl_down_sync(0xffffffffu, sl, o);
        sr += __shfl_down_sync(0xffffffffu, sr, o);
    }
    if (lane == 0) { g_el[gw] = sl; g_er[gw] = sr; }
}

// ---------------- per-dst softmax + weighted aggregation (+ residual) ----------------
__global__ void __launch_bounds__(256) k_agg(int d) {
    const int HD = 2 * d;
    int n = blockIdx.x;
    int tid = threadIdx.x;
    int start = g_indptr[n];
    int deg = g_indptr[n + 1] - start;
    __shared__ float s_m0, s_m1, s_i0, s_i1;
    __shared__ int s_src[32];
    __shared__ float s_w[32][2];
    float er0 = g_er[n * 2 + 0];
    float er1 = g_er[n * 2 + 1];

    if (tid < 32) {
        float m0 = -1e30f, m1 = -1e30f;
        for (int j = tid; j < deg; j += 32) {
            int s = g_esrc[start + j];
            float e0 = lrelu(g_el[s * 2 + 0] + er0, 0.2f);
            float e1 = lrelu(g_el[s * 2 + 1] + er1, 0.2f);
            m0 = fmaxf(m0, e0); m1 = fmaxf(m1, e1);
        }
#pragma unroll
        for (int o = 16; o > 0; o >>= 1) {
            m0 = fmaxf(m0, __shfl_xor_sync(0xffffffffu, m0, o));
            m1 = fmaxf(m1, __shfl_xor_sync(0xffffffffu, m1, o));
        }
        float z0 = 0.f, z1 = 0.f;
        for (int j = tid; j < deg; j += 32) {
            int s = g_esrc[start + j];
            float e0 = lrelu(g_el[s * 2 + 0] + er0, 0.2f);
            float e1 = lrelu(g_el[s * 2 + 1] + er1, 0.2f);
            z0 += expf(e0 - m0);
            z1 += expf(e1 - m1);
        }
#pragma unroll
        for (int o = 16; o > 0; o >>= 1) {
            z0 += __shfl_xor_sync(0xffffffffu, z0, o);
            z1 += __shfl_xor_sync(0xffffffffu, z1, o);
        }
        if (tid == 0) {
            s_m0 = m0; s_m1 = m1;
            s_i0 = (deg > 0) ? 1.f / z0 : 0.f;
            s_i1 = (deg > 0) ? 1.f / z1 : 0.f;
        }
    }
    __syncthreads();
    float m0 = s_m0, m1 = s_m1, i0 = s_i0, i1 = s_i1;

    float acc[4] = {0.f, 0.f, 0.f, 0.f};
    for (int c0 = 0; c0 < deg; c0 += 32) {
        int cn = min(32, deg - c0);
        if (tid < cn) {
            int s = g_esrc[start + c0 + tid];
            s_src[tid] = s;
            float e0 = lrelu(g_el[s * 2 + 0] + er0, 0.2f);
            float e1 = lrelu(g_el[s * 2 + 1] + er1, 0.2f);
            s_w[tid][0] = expf(e0 - m0) * i0;
            s_w[tid][1] = expf(e1 - m1) * i1;
        }
        __syncthreads();
        int j = 0;
        for (; j + 1 < cn; j += 2) {
            const float* h0 = g_h + (size_t)s_src[j] * HD;
            const float* h1 = g_h + (size_t)s_src[j + 1] * HD;
            float wa0 = s_w[j][0], wa1 = s_w[j][1];
            float wb0 = s_w[j + 1][0], wb1 = s_w[j + 1][1];
#pragma unroll
            for (int k = 0; k < 4; k++) {
                int c = tid + k * 256;
                if (c < HD) {
                    float wa = (c < d) ? wa0 : wa1;
                    float wb = (c < d) ? wb0 : wb1;
                    float v0 = __ldg(h0 + c);
                    float v1 = __ldg(h1 + c);
                    acc[k] = fmaf(wa, v0, acc[k]);
                    acc[k] = fmaf(wb, v1, acc[k]);
                }
            }
        }
        if (j < cn) {
            const float* h0 = g_h + (size_t)s_src[j] * HD;
            float wa0 = s_w[j][0], wa1 = s_w[j][1];
#pragma unroll
            for (int k = 0; k < 4; k++) {
                int c = tid + k * 256;
                if (c < HD) {
                    float wa = (c < d) ? wa0 : wa1;
                    acc[k] = fmaf(wa, __ldg(h0 + c), acc[k]);
                }
            }
        }
        __syncthreads();
    }
#pragma unroll
    for (int k = 0; k < 4; k++) {
        int c = tid + k * 256;
        if (c < HD) g_x[(size_t)n * HD + c] = acc[k] + g_r[(size_t)n * HD + c];
    }
}

// ---------------- GraphNorm stats: 32 rows/block, 128 threads, grid 1024 ----------------
__global__ void __launch_bounds__(128) k_colstats(int d) {
    int r0 = blockIdx.x * 32;
    int c4 = threadIdx.x;
    int q = d >> 2;
    if (c4 >= q) return;
    float a0 = 0.f, a1 = 0.f, a2 = 0.f, a3 = 0.f;
    float b0 = 0.f, b1 = 0.f, b2 = 0.f, b3 = 0.f;
    for (int r = 0; r < 32; r++) {
        const float4* row = (const float4*)(g_x + (size_t)(r0 + r) * d);
        float4 v = row[c4];
        a0 += v.x; b0 += v.x * v.x;
        a1 += v.y; b1 += v.y * v.y;
        a2 += v.z; b2 += v.z * v.z;
        a3 += v.w; b3 += v.w * v.w;
    }
    int c = c4 * 4;
    atomicAdd(&g_s1[c + 0], a0); atomicAdd(&g_s2[c + 0], b0);
    atomicAdd(&g_s1[c + 1], a1); atomicAdd(&g_s2[c + 1], b1);
    atomicAdd(&g_s1[c + 2], a2); atomicAdd(&g_s2[c + 2], b2);
    atomicAdd(&g_s1[c + 3], a3); atomicAdd(&g_s2[c + 3], b3);
}

__global__ void k_finstats(const float* __restrict__ gamma, const float* __restrict__ beta,
                           const float* __restrict__ alpha, int d) {
    int c = blockIdx.x * blockDim.x + threadIdx.x;
    if (c >= d) return;
    const float inv_nh = 1.f / (float)(NN * HH);
    float mean = g_s1[c] * inv_nh;
    float ex2 = g_s2[c] * inv_nh;
    float a = alpha[c];
    float var = ex2 - 2.f * a * mean * mean + a * a * mean * mean;
    float inv = rsqrtf(var + 1e-5f);
    float sc = gamma[c] * inv;
    g_scale[c] = sc;
    g_bias[c] = beta[c] - sc * a * mean;
}

// ---------------- normalize + lrelu + head-mean partials: 16 nodes/block, grid 1024 ----
__global__ void k_norm(const int* __restrict__ gid, int d, int off, int writeY) {
    int nb = blockIdx.x * 16;
    int g = gid[nb];
    int c0 = threadIdx.x, c1 = threadIdx.x + 256;
    float acc0 = 0.f, acc1 = 0.f;
    float sc0 = 0.f, bi0 = 0.f, sc1 = 0.f, bi1 = 0.f;
    if (c0 < d) { sc0 = g_scale[c0]; bi0 = g_bias[c0]; }
    if (c1 < d) { sc1 = g_scale[c1]; bi1 = g_bias[c1]; }
    for (int i = 0; i < 16; i++) {
        size_t base = (size_t)(nb + i) * 2 * d;
        if (c0 < d) {
            float y0 = lrelu(g_x[base + c0] * sc0 + bi0, 0.01f);
            float y1 = lrelu(g_x[base + d + c0] * sc0 + bi0, 0.01f);
            if (writeY) {
                g_y[base + c0] = y0;
                g_y[base + d + c0] = y1;
            }
            acc0 += y0 + y1;
        }
        if (c1 < d) {
            float y0 = lrelu(g_x[base + c1] * sc1 + bi1, 0.01f);
            float y1 = lrelu(g_x[base + d + c1] * sc1 + bi1, 0.01f);
            if (writeY) {
                g_y[base + c1] = y0;
                g_y[base + d + c1] = y1;
            }
            acc1 += y0 + y1;
        }
    }
    if (c0 < d) atomicAdd(&g_parts[g * OUTC + off + c0], acc0);
    if (c1 < d) atomicAdd(&g_parts[g * OUTC + off + c1], acc1);
}

// ---------------- final ----------------
__global__ void k_final(float* __restrict__ out) {
    int i = blockIdx.x * blockDim.x + threadIdx.x;
    if (i < BB * OUTC) {
        int b = i / OUTC;
        float v = g_parts[i] / (2.f * (float)g_counts[b]);
        out[i] = lrelu(v, 0.01f);
    }
}

// ---------------- launch ----------------
extern "C" void kernel_launch(void* const* d_in, const int* in_sizes, int n_in,
                              void* d_out, int out_size) {
    const float* nf = (const float*)d_in[0];
    const float* W[3]  = {(const float*)d_in[1],  (const float*)d_in[8],  (const float*)d_in[15]};
    const float* AL[3] = {(const float*)d_in[2],  (const float*)d_in[9],  (const float*)d_in[16]};
    const float* AR[3] = {(const float*)d_in[3],  (const float*)d_in[10], (const float*)d_in[17]};
    const float* RW[3] = {(const float*)d_in[4],  (const float*)d_in[11], (const float*)d_in[18]};
    const float* GA[3] = {(const float*)d_in[5],  (const float*)d_in[12], (const float*)d_in[19]};
    const float* BE[3] = {(const float*)d_in[6],  (const float*)d_in[13], (const float*)d_in[20]};
    const float* AP[3] = {(const float*)d_in[7],  (const float*)d_in[14], (const float*)d_in[21]};
    const int* src = (const int*)d_in[22];
    const int* dst = (const int*)d_in[23];
    const int* gid = (const int*)d_in[24];
    float* out = (float*)d_out;

    cudaFuncSetAttribute(k_mma, cudaFuncAttributeMaxDynamicSharedMemorySize, SMEM_BYTES);

    const int dims[3] = {128, 256, 512};
    const int offs[3] = {0, 128, 384};

    k_zero<<<(NN + 255) / 256, 256>>>();
    k_build<<<EE / 256, 256>>>(dst, gid);
    k_scan1<<<64, 256>>>();
    k_scan2<<<1, 64>>>();
    k_scan3<<<NN / 256, 256>>>();

    // layer 0 GEMM (independent of CSR)
    {
        dim3 gg(dims[0] * 2 / 128, NN / 128, 2);
        k_mma<<<gg, 256, SMEM_BYTES>>>(nf, 1, W[0], RW[0], dims[0], dims[0] * 2);
    }
    k_scatter<<<EE / 256, 256>>>(src, dst);

    for (int l = 0; l < 3; l++) {
        int d = dims[l], in = d, HD = 2 * d;
        if (l > 0) {
            dim3 gg(HD / 128, NN / 128, 2);
            k_mma<<<gg, 256, SMEM_BYTES>>>(nf, 0, W[l], RW[l], in, HD);
        }
        k_attn<<<(NN * HH * 32) / 256, 256>>>(AL[l], AR[l], d);
        k_agg<<<NN, 256>>>(d);
        k_colstats<<<(NN * HH) / 32, 128>>>(d);
        k_finstats<<<(d + 255) / 256, 256>>>(GA[l], BE[l], AP[l], d);
        k_norm<<<NN / 16, 256>>>(gid, d, offs[l], (l < 2) ? 1 : 0);
    }
    k_final<<<(BB * OUTC + 255) / 256, 256>>>(out);
}

// round 11
// speedup vs baseline: 1.1160x; 1.1160x over previous
#include <cuda_runtime.h>
#include <cuda_fp16.h>
#include <math.h>
#include <stdint.h>

#define NN 16384
#define EE 131072
#define BB 16
#define HH 2
#define MAXD 512
#define MAXHD 1024
#define OUTC 896

// ---------------- scratch (device globals; no allocation) ----------------
__device__ float g_x[(size_t)NN * MAXHD];
__device__ __half g_abf[(size_t)NN * MAXD];      // fp16 GEMM input (A)
__device__ __half g_wTa[(size_t)MAXD * MAXHD];   // fp16 W transposed [N][K]
__device__ __half g_wTb[(size_t)MAXD * MAXHD];   // fp16 rW transposed [N][K]
__device__ float g_h[(size_t)NN * MAXHD];
__device__ float g_r[(size_t)NN * MAXHD];
__device__ float g_el[NN * HH];
__device__ float g_er[NN * HH];
__device__ int   g_indptr[NN + 1];
__device__ int   g_cnt[NN];
__device__ int   g_cur[NN];
__device__ int   g_esrc[EE];
__device__ int   g_bsum[64];
__device__ int   g_boff[64];
__device__ float g_s1[MAXD];
__device__ float g_s2[MAXD];
__device__ float g_scale[MAXD];
__device__ float g_bias[MAXD];
__device__ float g_parts[BB * OUTC];
__device__ int   g_counts[BB];

__device__ __forceinline__ float lrelu(float v, float s) { return v > 0.f ? v : s * v; }

__device__ __forceinline__ void cp_async16(uint32_t saddr, const void* gptr) {
    asm volatile("cp.async.cg.shared.global [%0], [%1], 16;" :: "r"(saddr), "l"(gptr));
}
__device__ __forceinline__ void cp_commit() { asm volatile("cp.async.commit_group;"); }

// ---------------- front ----------------
__global__ void k_zero() {
    int i = blockIdx.x * blockDim.x + threadIdx.x;
    if (i < BB * OUTC) g_parts[i] = 0.f;
    if (i < BB) g_counts[i] = 0;
    if (i < NN) g_cnt[i] = 0;
}

__global__ void k_build(const int* __restrict__ dst, const int* __restrict__ gid) {
    int i = blockIdx.x * blockDim.x + threadIdx.x;
    if (i < EE) atomicAdd(&g_cnt[dst[i]], 1);
    if (i < NN) atomicAdd(&g_counts[gid[i]], 1);
}

__global__ void k_scan1() {
    __shared__ int sm[256];
    int tid = threadIdx.x;
    int i = blockIdx.x * 256 + tid;
    int v = g_cnt[i];
    sm[tid] = v;
    __syncthreads();
    for (int off = 1; off < 256; off <<= 1) {
        int t = (tid >= off) ? sm[tid - off] : 0;
        __syncthreads();
        sm[tid] += t;
        __syncthreads();
    }
    g_indptr[i] = sm[tid] - v;
    g_cur[i] = 0;
    if (tid == 255) g_bsum[blockIdx.x] = sm[255];
}

__global__ void k_scan2() {
    __shared__ int sm[64];
    int tid = threadIdx.x;
    int v = g_bsum[tid];
    sm[tid] = v;
    __syncthreads();
    for (int off = 1; off < 64; off <<= 1) {
        int t = (tid >= off) ? sm[tid - off] : 0;
        __syncthreads();
        sm[tid] += t;
        __syncthreads();
    }
    g_boff[tid] = sm[tid] - v;
    if (tid == 63) g_indptr[NN] = sm[63];
}

__global__ void k_scan3() {
    int i = blockIdx.x * blockDim.x + threadIdx.x;
    if (i < NN) g_indptr[i] += g_boff[i >> 8];
}

__global__ void k_scatter(const int* __restrict__ src, const int* __restrict__ dst) {
    int i = blockIdx.x * blockDim.x + threadIdx.x;
    if (i < EE) {
        int d = dst[i];
        int p = g_indptr[d] + atomicAdd(&g_cur[d], 1);
        g_esrc[p] = src[i];
    }
}

// ---------------- fp32 -> fp16 conversions ----------------
__global__ void k_cvtA(const float* __restrict__ src, int n4) {  // n4 = total/4
    int i = blockIdx.x * blockDim.x + threadIdx.x;
    if (i < n4) {
        float4 v = reinterpret_cast<const float4*>(src)[i];
        __half2* o = reinterpret_cast<__half2*>(g_abf);
        o[2 * i + 0] = __floats2half2_rn(v.x, v.y);
        o[2 * i + 1] = __floats2half2_rn(v.z, v.w);
    }
}

// transpose + convert: src [K][N] fp32 -> dst [N][K] fp16. z=0: W->g_wTa, z=1: rW->g_wTb
__global__ void k_cvtW(const float* __restrict__ W, const float* __restrict__ R,
                       int K, int N) {
    __shared__ float t[32][33];
    const float* S = blockIdx.z ? R : W;
    __half* D = blockIdx.z ? g_wTb : g_wTa;
    int n0 = blockIdx.x * 32, k0 = blockIdx.y * 32;
    for (int r = threadIdx.y; r < 32; r += 8)
        t[r][threadIdx.x] = S[(size_t)(k0 + r) * N + n0 + threadIdx.x];
    __syncthreads();
    for (int r = threadIdx.y; r < 32; r += 8)
        D[(size_t)(n0 + r) * K + k0 + threadIdx.x] = __float2half(t[threadIdx.x][r]);
}

// ---------------- FP16 tensor-core GEMM (m16n8k16), 3-stage cp.async ----------------
// C[M,Nc] = A[M,K](fp16) @ B[K,Nc] (B stored transposed fp16 [Nc][K]).
// Block 128x128, BK=16. blockIdx.z: 0 -> B=g_wTa, C=g_h; 1 -> B=g_wTb, C=g_r.
__global__ void __launch_bounds__(256) k_mma(int K, int Nc) {
    __shared__ __align__(16) __half As[3][128][24];
    __shared__ __align__(16) __half Bs[3][128][24];

    const __half* A = g_abf;
    const __half* BT = blockIdx.z ? g_wTb : g_wTa;
    float* C = blockIdx.z ? g_r : g_h;

    int tid = threadIdx.x;
    int lane = tid & 31;
    int warp = tid >> 5;
    int wm = (warp >> 1) * 32;
    int wn = (warp & 1) * 64;
    int rowT = blockIdx.y * 128;
    int colT = blockIdx.x * 128;
    int gr = lane >> 2;
    int tg = lane & 3;

    int ldRow = tid >> 1;        // 0..127
    int ldChunk = (tid & 1) * 8; // 0 or 8 halves (16B)

    float acc[2][8][4];
#pragma unroll
    for (int i = 0; i < 2; i++)
#pragma unroll
        for (int j = 0; j < 8; j++)
#pragma unroll
            for (int c = 0; c < 4; c++) acc[i][j][c] = 0.f;

    int iters = K >> 4;   // 8 / 16 / 32

    auto load_stage = [&](int s, int kt) {
        uint32_t sa = (uint32_t)__cvta_generic_to_shared(&As[s][ldRow][ldChunk]);
        cp_async16(sa, A + (size_t)(rowT + ldRow) * K + kt + ldChunk);
        uint32_t sb = (uint32_t)__cvta_generic_to_shared(&Bs[s][ldRow][ldChunk]);
        cp_async16(sb, BT + (size_t)(colT + ldRow) * K + kt + ldChunk);
    };

    load_stage(0, 0);
    cp_commit();
    load_stage(1, 16);
    cp_commit();

    for (int it = 0; it < iters; it++) {
        if (it + 1 < iters) asm volatile("cp.async.wait_group 1;");
        else                asm volatile("cp.async.wait_group 0;");
        __syncthreads();

        if (it + 2 < iters) {
            load_stage((it + 2) % 3, (it + 2) << 4);
            cp_commit();
        }

        int cur = it % 3;
        uint32_t af[2][4];
#pragma unroll
        for (int i = 0; i < 2; i++) {
            int m0 = wm + i * 16 + gr;
            af[i][0] = *reinterpret_cast<const uint32_t*>(&As[cur][m0][2 * tg]);
            af[i][1] = *reinterpret_cast<const uint32_t*>(&As[cur][m0 + 8][2 * tg]);
            af[i][2] = *reinterpret_cast<const uint32_t*>(&As[cur][m0][2 * tg + 8]);
            af[i][3] = *reinterpret_cast<const uint32_t*>(&As[cur][m0 + 8][2 * tg + 8]);
        }
        uint32_t bf[8][2];
#pragma unroll
        for (int j = 0; j < 8; j++) {
            int n0 = wn + j * 8 + gr;
            bf[j][0] = *reinterpret_cast<const uint32_t*>(&Bs[cur][n0][2 * tg]);
            bf[j][1] = *reinterpret_cast<const uint32_t*>(&Bs[cur][n0][2 * tg + 8]);
        }
#pragma unroll
        for (int i = 0; i < 2; i++)
#pragma unroll
            for (int j = 0; j < 8; j++) {
                asm volatile(
                    "mma.sync.aligned.m16n8k16.row.col.f32.f16.f16.f32 "
                    "{%0,%1,%2,%3},{%4,%5,%6,%7},{%8,%9},{%0,%1,%2,%3};"
                    : "+f"(acc[i][j][0]), "+f"(acc[i][j][1]),
                      "+f"(acc[i][j][2]), "+f"(acc[i][j][3])
                    : "r"(af[i][0]), "r"(af[i][1]), "r"(af[i][2]), "r"(af[i][3]),
                      "r"(bf[j][0]), "r"(bf[j][1]));
            }
        __syncthreads();
    }

#pragma unroll
    for (int i = 0; i < 2; i++) {
        int r0 = rowT + wm + i * 16 + gr;
#pragma unroll
        for (int j = 0; j < 8; j++) {
            int ccol = colT + wn + j * 8 + tg * 2;
            *reinterpret_cast<float2*>(C + (size_t)r0 * Nc + ccol) =
                make_float2(acc[i][j][0], acc[i][j][1]);
            *reinterpret_cast<float2*>(C + (size_t)(r0 + 8) * Nc + ccol) =
                make_float2(acc[i][j][2], acc[i][j][3]);
        }
    }
}

// ---------------- attention projections el/er (+ zero s1/s2, FULL range) ----------------
__global__ void k_attn(const float* __restrict__ al, const float* __restrict__ ar, int d) {
    if (blockIdx.x == 0) {
        g_s1[threadIdx.x] = 0.f;
        g_s1[threadIdx.x + 256] = 0.f;
        g_s2[threadIdx.x] = 0.f;
        g_s2[threadIdx.x + 256] = 0.f;
    }
    int gw = (blockIdx.x * blockDim.x + threadIdx.x) >> 5;
    int lane = threadIdx.x & 31;
    if (gw >= NN * HH) return;
    int n = gw >> 1, hd = gw & 1;
    const float4* hr = (const float4*)(g_h + (size_t)n * (2 * d) + hd * d);
    const float4* av = (const float4*)(al + hd * d);
    const float4* bv = (const float4*)(ar + hd * d);
    int q = d >> 2;
    float sl = 0.f, sr = 0.f;
    for (int c = lane; c < q; c += 32) {
        float4 v = hr[c], a = av[c], b = bv[c];
        sl += v.x * a.x + v.y * a.y + v.z * a.z + v.w * a.w;
        sr += v.x * b.x + v.y * b.y + v.z * b.z + v.w * b.w;
    }
#pragma unroll
    for (int o = 16; o > 0; o >>= 1) {
        sl += __shfl_down_sync(0xffffffffu, sl, o);
        sr += __shfl_down_sync(0xffffffffu, sr, o);
    }
    if (lane == 0) { g_el[gw] = sl; g_er[gw] = sr; }
}

// ---------------- per-dst softmax + weighted aggregation (+ residual) ----------------
__global__ void __launch_bounds__(256) k_agg(int d) {
    const int HD = 2 * d;
    int n = blockIdx.x;
    int tid = threadIdx.x;
    int start = g_indptr[n];
    int deg = g_indptr[n + 1] - start;
    __shared__ float s_m0, s_m1, s_i0, s_i1;
    __shared__ int s_src[32];
    __shared__ float s_w[32][2];
    float er0 = g_er[n * 2 + 0];
    float er1 = g_er[n * 2 + 1];

    if (tid < 32) {
        float m0 = -1e30f, m1 = -1e30f;
        for (int j = tid; j < deg; j += 32) {
            int s = g_esrc[start + j];
            float e0 = lrelu(g_el[s * 2 + 0] + er0, 0.2f);
            float e1 = lrelu(g_el[s * 2 + 1] + er1, 0.2f);
            m0 = fmaxf(m0, e0); m1 = fmaxf(m1, e1);
        }
#pragma unroll
        for (int o = 16; o > 0; o >>= 1) {
            m0 = fmaxf(m0, __shfl_xor_sync(0xffffffffu, m0, o));
            m1 = fmaxf(m1, __shfl_xor_sync(0xffffffffu, m1, o));
        }
        float z0 = 0.f, z1 = 0.f;
        for (int j = tid; j < deg; j += 32) {
            int s = g_esrc[start + j];
            float e0 = lrelu(g_el[s * 2 + 0] + er0, 0.2f);
            float e1 = lrelu(g_el[s * 2 + 1] + er1, 0.2f);
            z0 += expf(e0 - m0);
            z1 += expf(e1 - m1);
        }
#pragma unroll
        for (int o = 16; o > 0; o >>= 1) {
            z0 += __shfl_xor_sync(0xffffffffu, z0, o);
            z1 += __shfl_xor_sync(0xffffffffu, z1, o);
        }
        if (tid == 0) {
            s_m0 = m0; s_m1 = m1;
            s_i0 = (deg > 0) ? 1.f / z0 : 0.f;
            s_i1 = (deg > 0) ? 1.f / z1 : 0.f;
        }
    }
    __syncthreads();
    float m0 = s_m0, m1 = s_m1, i0 = s_i0, i1 = s_i1;

    float acc[4] = {0.f, 0.f, 0.f, 0.f};
    for (int c0 = 0; c0 < deg; c0 += 32) {
        int cn = min(32, deg - c0);
        if (tid < cn) {
            int s = g_esrc[start + c0 + tid];
            s_src[tid] = s;
            float e0 = lrelu(g_el[s * 2 + 0] + er0, 0.2f);
            float e1 = lrelu(g_el[s * 2 + 1] + er1, 0.2f);
            s_w[tid][0] = expf(e0 - m0) * i0;
            s_w[tid][1] = expf(e1 - m1) * i1;
        }
        __syncthreads();
        int j = 0;
        for (; j + 1 < cn; j += 2) {
            const float* h0 = g_h + (size_t)s_src[j] * HD;
            const float* h1 = g_h + (size_t)s_src[j + 1] * HD;
            float wa0 = s_w[j][0], wa1 = s_w[j][1];
            float wb0 = s_w[j + 1][0], wb1 = s_w[j + 1][1];
#pragma unroll
            for (int k = 0; k < 4; k++) {
                int c = tid + k * 256;
                if (c < HD) {
                    float wa = (c < d) ? wa0 : wa1;
                    float wb = (c < d) ? wb0 : wb1;
                    float v0 = __ldg(h0 + c);
                    float v1 = __ldg(h1 + c);
                    acc[k] = fmaf(wa, v0, acc[k]);
                    acc[k] = fmaf(wb, v1, acc[k]);
                }
            }
        }
        if (j < cn) {
            const float* h0 = g_h + (size_t)s_src[j] * HD;
            float wa0 = s_w[j][0], wa1 = s_w[j][1];
#pragma unroll
            for (int k = 0; k < 4; k++) {
                int c = tid + k * 256;
                if (c < HD) {
                    float wa = (c < d) ? wa0 : wa1;
                    acc[k] = fmaf(wa, __ldg(h0 + c), acc[k]);
                }
            }
        }
        __syncthreads();
    }
#pragma unroll
    for (int k = 0; k < 4; k++) {
        int c = tid + k * 256;
        if (c < HD) g_x[(size_t)n * HD + c] = acc[k] + g_r[(size_t)n * HD + c];
    }
}

// ---------------- GraphNorm stats ----------------
__global__ void __launch_bounds__(128) k_colstats(int d) {
    int r0 = blockIdx.x * 32;
    int c4 = threadIdx.x;
    int q = d >> 2;
    if (c4 >= q) return;
    float a0 = 0.f, a1 = 0.f, a2 = 0.f, a3 = 0.f;
    float b0 = 0.f, b1 = 0.f, b2 = 0.f, b3 = 0.f;
    for (int r = 0; r < 32; r++) {
        const float4* row = (const float4*)(g_x + (size_t)(r0 + r) * d);
        float4 v = row[c4];
        a0 += v.x; b0 += v.x * v.x;
        a1 += v.y; b1 += v.y * v.y;
        a2 += v.z; b2 += v.z * v.z;
        a3 += v.w; b3 += v.w * v.w;
    }
    int c = c4 * 4;
    atomicAdd(&g_s1[c + 0], a0); atomicAdd(&g_s2[c + 0], b0);
    atomicAdd(&g_s1[c + 1], a1); atomicAdd(&g_s2[c + 1], b1);
    atomicAdd(&g_s1[c + 2], a2); atomicAdd(&g_s2[c + 2], b2);
    atomicAdd(&g_s1[c + 3], a3); atomicAdd(&g_s2[c + 3], b3);
}

__global__ void k_finstats(const float* __restrict__ gamma, const float* __restrict__ beta,
                           const float* __restrict__ alpha, int d) {
    int c = blockIdx.x * blockDim.x + threadIdx.x;
    if (c >= d) return;
    const float inv_nh = 1.f / (float)(NN * HH);
    float mean = g_s1[c] * inv_nh;
    float ex2 = g_s2[c] * inv_nh;
    float a = alpha[c];
    float var = ex2 - 2.f * a * mean * mean + a * a * mean * mean;
    float inv = rsqrtf(var + 1e-5f);
    float sc = gamma[c] * inv;
    g_scale[c] = sc;
    g_bias[c] = beta[c] - sc * a * mean;
}

// ---------------- normalize + lrelu + head-mean partials (fp16 next-layer input) ------
__global__ void k_norm(const int* __restrict__ gid, int d, int off, int writeY) {
    int nb = blockIdx.x * 16;
    int g = gid[nb];
    int c0 = threadIdx.x, c1 = threadIdx.x + 256;
    float acc0 = 0.f, acc1 = 0.f;
    float sc0 = 0.f, bi0 = 0.f, sc1 = 0.f, bi1 = 0.f;
    if (c0 < d) { sc0 = g_scale[c0]; bi0 = g_bias[c0]; }
    if (c1 < d) { sc1 = g_scale[c1]; bi1 = g_bias[c1]; }
    for (int i = 0; i < 16; i++) {
        size_t base = (size_t)(nb + i) * 2 * d;
        if (c0 < d) {
            float y0 = lrelu(g_x[base + c0] * sc0 + bi0, 0.01f);
            float y1 = lrelu(g_x[base + d + c0] * sc0 + bi0, 0.01f);
            if (writeY) {
                g_abf[base + c0] = __float2half(y0);
                g_abf[base + d + c0] = __float2half(y1);
            }
            acc0 += y0 + y1;
        }
        if (c1 < d) {
            float y0 = lrelu(g_x[base + c1] * sc1 + bi1, 0.01f);
            float y1 = lrelu(g_x[base + d + c1] * sc1 + bi1, 0.01f);
            if (writeY) {
                g_abf[base + c1] = __float2half(y0);
                g_abf[base + d + c1] = __float2half(y1);
            }
            acc1 += y0 + y1;
        }
    }
    if (c0 < d) atomicAdd(&g_parts[g * OUTC + off + c0], acc0);
    if (c1 < d) atomicAdd(&g_parts[g * OUTC + off + c1], acc1);
}

// ---------------- final ----------------
__global__ void k_final(float* __restrict__ out) {
    int i = blockIdx.x * blockDim.x + threadIdx.x;
    if (i < BB * OUTC) {
        int b = i / OUTC;
        float v = g_parts[i] / (2.f * (float)g_counts[b]);
        out[i] = lrelu(v, 0.01f);
    }
}

// ---------------- launch ----------------
extern "C" void kernel_launch(void* const* d_in, const int* in_sizes, int n_in,
                              void* d_out, int out_size) {
    const float* nf = (const float*)d_in[0];
    const float* W[3]  = {(const float*)d_in[1],  (const float*)d_in[8],  (const float*)d_in[15]};
    const float* AL[3] = {(const float*)d_in[2],  (const float*)d_in[9],  (const float*)d_in[16]};
    const float* AR[3] = {(const float*)d_in[3],  (const float*)d_in[10], (const float*)d_in[17]};
    const float* RW[3] = {(const float*)d_in[4],  (const float*)d_in[11], (const float*)d_in[18]};
    const float* GA[3] = {(const float*)d_in[5],  (const float*)d_in[12], (const float*)d_in[19]};
    const float* BE[3] = {(const float*)d_in[6],  (const float*)d_in[13], (const float*)d_in[20]};
    const float* AP[3] = {(const float*)d_in[7],  (const float*)d_in[14], (const float*)d_in[21]};
    const int* src = (const int*)d_in[22];
    const int* dst = (const int*)d_in[23];
    const int* gid = (const int*)d_in[24];
    float* out = (float*)d_out;

    const int dims[3] = {128, 256, 512};
    const int offs[3] = {0, 128, 384};

    k_zero<<<(NN + 255) / 256, 256>>>();
    k_build<<<EE / 256, 256>>>(dst, gid);
    k_scan1<<<64, 256>>>();
    k_scan2<<<1, 64>>>();
    k_scan3<<<NN / 256, 256>>>();

    // layer-0 A conversion + weight transposes + GEMM
    k_cvtA<<<(NN * 128 / 4 + 255) / 256, 256>>>(nf, NN * 128 / 4);
    {
        dim3 tg(32, 8);
        dim3 wg(dims[0] * 2 / 32, dims[0] / 32, 2);
        k_cvtW<<<wg, tg>>>(W[0], RW[0], dims[0], dims[0] * 2);
        dim3 gg(dims[0] * 2 / 128, NN / 128, 2);
        k_mma<<<gg, 256>>>(dims[0], dims[0] * 2);
    }
    k_scatter<<<EE / 256, 256>>>(src, dst);

    for (int l = 0; l < 3; l++) {
        int d = dims[l], HD = 2 * d;
        if (l > 0) {
            dim3 tg(32, 8);
            dim3 wg(HD / 32, d / 32, 2);
            k_cvtW<<<wg, tg>>>(W[l], RW[l], d, HD);
            dim3 gg(HD / 128, NN / 128, 2);
            k_mma<<<gg, 256>>>(d, HD);
        }
        k_attn<<<(NN * HH * 32) / 256, 256>>>(AL[l], AR[l], d);
        k_agg<<<NN, 256>>>(d);
        k_colstats<<<(NN * HH) / 32, 128>>>(d);
        k_finstats<<<(d + 255) / 256, 256>>>(GA[l], BE[l], AP[l], d);
        k_norm<<<NN / 16, 256>>>(gid, d, offs[l], (l < 2) ? 1 : 0);
    }
    k_final<<<(BB * OUTC + 255) / 256, 256>>>(out);
}

// round 13
// speedup vs baseline: 1.2501x; 1.1202x over previous
#include <cuda_runtime.h>
#include <cuda_fp16.h>
#include <math.h>
#include <stdint.h>

#define NN 16384
#define EE 131072
#define BB 16
#define HH 2
#define MAXD 512
#define MAXHD 1024
#define OUTC 896

// ---------------- scratch (device globals; no allocation) ----------------
__device__ float g_x[(size_t)NN * MAXHD];
__device__ __half g_abf[(size_t)NN * MAXD];      // fp16 GEMM input (A)
__device__ __half g_wTa[(size_t)MAXD * MAXHD];   // fp16 W transposed [N][K]
__device__ __half g_wTb[(size_t)MAXD * MAXHD];   // fp16 rW transposed [N][K]
__device__ __half g_h[(size_t)NN * MAXHD];       // fp16 h = x @ W  (gathered by agg)
__device__ float g_r[(size_t)NN * MAXHD];        // fp32 residual
__device__ float g_el[NN * HH];
__device__ float g_er[NN * HH];
__device__ int   g_indptr[NN + 1];
__device__ int   g_cnt[NN];
__device__ int   g_cur[NN];
__device__ int   g_esrc[EE];
__device__ int   g_bsum[64];
__device__ int   g_boff[64];
__device__ float g_s1[MAXD];
__device__ float g_s2[MAXD];
__device__ float g_scale[MAXD];
__device__ float g_bias[MAXD];
__device__ float g_parts[BB * OUTC];
__device__ int   g_counts[BB];

__device__ __forceinline__ float lrelu(float v, float s) { return v > 0.f ? v : s * v; }

__device__ __forceinline__ void cp_async16(uint32_t saddr, const void* gptr) {
    asm volatile("cp.async.cg.shared.global [%0], [%1], 16;" :: "r"(saddr), "l"(gptr));
}
__device__ __forceinline__ void cp_commit() { asm volatile("cp.async.commit_group;"); }

// ---------------- front ----------------
__global__ void k_zero() {
    int i = blockIdx.x * blockDim.x + threadIdx.x;
    if (i < BB * OUTC) g_parts[i] = 0.f;
    if (i < BB) g_counts[i] = 0;
    if (i < NN) g_cnt[i] = 0;
}

__global__ void k_build(const int* __restrict__ dst, const int* __restrict__ gid) {
    int i = blockIdx.x * blockDim.x + threadIdx.x;
    if (i < EE) atomicAdd(&g_cnt[dst[i]], 1);
    if (i < NN) atomicAdd(&g_counts[gid[i]], 1);
}

__global__ void k_scan1() {
    __shared__ int sm[256];
    int tid = threadIdx.x;
    int i = blockIdx.x * 256 + tid;
    int v = g_cnt[i];
    sm[tid] = v;
    __syncthreads();
    for (int off = 1; off < 256; off <<= 1) {
        int t = (tid >= off) ? sm[tid - off] : 0;
        __syncthreads();
        sm[tid] += t;
        __syncthreads();
    }
    g_indptr[i] = sm[tid] - v;
    g_cur[i] = 0;
    if (tid == 255) g_bsum[blockIdx.x] = sm[255];
}

__global__ void k_scan2() {
    __shared__ int sm[64];
    int tid = threadIdx.x;
    int v = g_bsum[tid];
    sm[tid] = v;
    __syncthreads();
    for (int off = 1; off < 64; off <<= 1) {
        int t = (tid >= off) ? sm[tid - off] : 0;
        __syncthreads();
        sm[tid] += t;
        __syncthreads();
    }
    g_boff[tid] = sm[tid] - v;
    if (tid == 63) g_indptr[NN] = sm[63];
}

__global__ void k_scan3() {
    int i = blockIdx.x * blockDim.x + threadIdx.x;
    if (i < NN) g_indptr[i] += g_boff[i >> 8];
}

__global__ void k_scatter(const int* __restrict__ src, const int* __restrict__ dst) {
    int i = blockIdx.x * blockDim.x + threadIdx.x;
    if (i < EE) {
        int d = dst[i];
        int p = g_indptr[d] + atomicAdd(&g_cur[d], 1);
        g_esrc[p] = src[i];
    }
}

// ---------------- fp32 -> fp16 conversions ----------------
__global__ void k_cvtA(const float* __restrict__ src, int n4) {
    int i = blockIdx.x * blockDim.x + threadIdx.x;
    if (i < n4) {
        float4 v = reinterpret_cast<const float4*>(src)[i];
        __half2* o = reinterpret_cast<__half2*>(g_abf);
        o[2 * i + 0] = __floats2half2_rn(v.x, v.y);
        o[2 * i + 1] = __floats2half2_rn(v.z, v.w);
    }
}

__global__ void k_cvtW(const float* __restrict__ W, const float* __restrict__ R,
                       int K, int N) {
    __shared__ float t[32][33];
    const float* S = blockIdx.z ? R : W;
    __half* D = blockIdx.z ? g_wTb : g_wTa;
    int n0 = blockIdx.x * 32, k0 = blockIdx.y * 32;
    for (int r = threadIdx.y; r < 32; r += 8)
        t[r][threadIdx.x] = S[(size_t)(k0 + r) * N + n0 + threadIdx.x];
    __syncthreads();
    for (int r = threadIdx.y; r < 32; r += 8)
        D[(size_t)(n0 + r) * K + k0 + threadIdx.x] = __float2half(t[threadIdx.x][r]);
}

// ---------------- FP16 tensor-core GEMM (m16n8k16), 3-stage cp.async ----------------
// Block 128x128, BK=16. z=0: C=g_h (fp16), z=1: C=g_r (fp32).
__global__ void __launch_bounds__(256) k_mma(int K, int Nc) {
    __shared__ __align__(16) __half As[3][128][24];
    __shared__ __align__(16) __half Bs[3][128][24];

    const __half* A = g_abf;
    const __half* BT = blockIdx.z ? g_wTb : g_wTa;

    int tid = threadIdx.x;
    int lane = tid & 31;
    int warp = tid >> 5;
    int wm = (warp >> 1) * 32;
    int wn = (warp & 1) * 64;
    int rowT = blockIdx.y * 128;
    int colT = blockIdx.x * 128;
    int gr = lane >> 2;
    int tg = lane & 3;

    int ldRow = tid >> 1;
    int ldChunk = (tid & 1) * 8;

    float acc[2][8][4];
#pragma unroll
    for (int i = 0; i < 2; i++)
#pragma unroll
        for (int j = 0; j < 8; j++)
#pragma unroll
            for (int c = 0; c < 4; c++) acc[i][j][c] = 0.f;

    int iters = K >> 4;

    auto load_stage = [&](int s, int kt) {
        uint32_t sa = (uint32_t)__cvta_generic_to_shared(&As[s][ldRow][ldChunk]);
        cp_async16(sa, A + (size_t)(rowT + ldRow) * K + kt + ldChunk);
        uint32_t sb = (uint32_t)__cvta_generic_to_shared(&Bs[s][ldRow][ldChunk]);
        cp_async16(sb, BT + (size_t)(colT + ldRow) * K + kt + ldChunk);
    };

    load_stage(0, 0);
    cp_commit();
    load_stage(1, 16);
    cp_commit();

    for (int it = 0; it < iters; it++) {
        if (it + 1 < iters) asm volatile("cp.async.wait_group 1;");
        else                asm volatile("cp.async.wait_group 0;");
        __syncthreads();

        if (it + 2 < iters) {
            load_stage((it + 2) % 3, (it + 2) << 4);
            cp_commit();
        }

        int cur = it % 3;
        uint32_t af[2][4];
#pragma unroll
        for (int i = 0; i < 2; i++) {
            int m0 = wm + i * 16 + gr;
            af[i][0] = *reinterpret_cast<const uint32_t*>(&As[cur][m0][2 * tg]);
            af[i][1] = *reinterpret_cast<const uint32_t*>(&As[cur][m0 + 8][2 * tg]);
            af[i][2] = *reinterpret_cast<const uint32_t*>(&As[cur][m0][2 * tg + 8]);
            af[i][3] = *reinterpret_cast<const uint32_t*>(&As[cur][m0 + 8][2 * tg + 8]);
        }
        uint32_t bf[8][2];
#pragma unroll
        for (int j = 0; j < 8; j++) {
            int n0 = wn + j * 8 + gr;
            bf[j][0] = *reinterpret_cast<const uint32_t*>(&Bs[cur][n0][2 * tg]);
            bf[j][1] = *reinterpret_cast<const uint32_t*>(&Bs[cur][n0][2 * tg + 8]);
        }
#pragma unroll
        for (int i = 0; i < 2; i++)
#pragma unroll
            for (int j = 0; j < 8; j++) {
                asm volatile(
                    "mma.sync.aligned.m16n8k16.row.col.f32.f16.f16.f32 "
                    "{%0,%1,%2,%3},{%4,%5,%6,%7},{%8,%9},{%0,%1,%2,%3};"
                    : "+f"(acc[i][j][0]), "+f"(acc[i][j][1]),
                      "+f"(acc[i][j][2]), "+f"(acc[i][j][3])
                    : "r"(af[i][0]), "r"(af[i][1]), "r"(af[i][2]), "r"(af[i][3]),
                      "r"(bf[j][0]), "r"(bf[j][1]));
            }
        __syncthreads();
    }

    if (blockIdx.z == 0) {
        // h output in fp16 (half2 per acc pair)
#pragma unroll
        for (int i = 0; i < 2; i++) {
            int r0 = rowT + wm + i * 16 + gr;
#pragma unroll
            for (int j = 0; j < 8; j++) {
                int ccol = colT + wn + j * 8 + tg * 2;
                *reinterpret_cast<__half2*>(g_h + (size_t)r0 * Nc + ccol) =
                    __floats2half2_rn(acc[i][j][0], acc[i][j][1]);
                *reinterpret_cast<__half2*>(g_h + (size_t)(r0 + 8) * Nc + ccol) =
                    __floats2half2_rn(acc[i][j][2], acc[i][j][3]);
            }
        }
    } else {
#pragma unroll
        for (int i = 0; i < 2; i++) {
            int r0 = rowT + wm + i * 16 + gr;
#pragma unroll
            for (int j = 0; j < 8; j++) {
                int ccol = colT + wn + j * 8 + tg * 2;
                *reinterpret_cast<float2*>(g_r + (size_t)r0 * Nc + ccol) =
                    make_float2(acc[i][j][0], acc[i][j][1]);
                *reinterpret_cast<float2*>(g_r + (size_t)(r0 + 8) * Nc + ccol) =
                    make_float2(acc[i][j][2], acc[i][j][3]);
            }
        }
    }
}

// ---------------- attention projections el/er from fp16 h (+ zero s1/s2) -------------
__global__ void k_attn(const float* __restrict__ al, const float* __restrict__ ar, int d) {
    if (blockIdx.x == 0) {
        g_s1[threadIdx.x] = 0.f;
        g_s1[threadIdx.x + 256] = 0.f;
        g_s2[threadIdx.x] = 0.f;
        g_s2[threadIdx.x + 256] = 0.f;
    }
    int gw = (blockIdx.x * blockDim.x + threadIdx.x) >> 5;
    int lane = threadIdx.x & 31;
    if (gw >= NN * HH) return;
    int n = gw >> 1, hd = gw & 1;
    const __half2* hr = (const __half2*)(g_h + (size_t)n * (2 * d) + hd * d);
    const float2* av = (const float2*)(al + hd * d);
    const float2* bv = (const float2*)(ar + hd * d);
    int q = d >> 1;
    float sl = 0.f, sr = 0.f;
    for (int c = lane; c < q; c += 32) {
        float2 v = __half22float2(hr[c]);
        float2 a = av[c], b = bv[c];
        sl += v.x * a.x + v.y * a.y;
        sr += v.x * b.x + v.y * b.y;
    }
#pragma unroll
    for (int o = 16; o > 0; o >>= 1) {
        sl += __shfl_down_sync(0xffffffffu, sl, o);
        sr += __shfl_down_sync(0xffffffffu, sr, o);
    }
    if (lane == 0) { g_el[gw] = sl; g_er[gw] = sr; }
}

// ---------------- per-dst softmax + fp16 gather aggregation (+ fp32 residual) ---------
__global__ void __launch_bounds__(256) k_agg(int d) {
    const int HD = 2 * d;
    int n = blockIdx.x;
    int tid = threadIdx.x;
    int start = g_indptr[n];
    int deg = g_indptr[n + 1] - start;
    __shared__ float s_m0, s_m1, s_i0, s_i1;
    __shared__ int s_src[32];
    __shared__ float s_w[32][2];
    float er0 = g_er[n * 2 + 0];
    float er1 = g_er[n * 2 + 1];

    if (tid < 32) {
        float m0 = -1e30f, m1 = -1e30f;
        for (int j = tid; j < deg; j += 32) {
            int s = g_esrc[start + j];
            float e0 = lrelu(g_el[s * 2 + 0] + er0, 0.2f);
            float e1 = lrelu(g_el[s * 2 + 1] + er1, 0.2f);
            m0 = fmaxf(m0, e0); m1 = fmaxf(m1, e1);
        }
#pragma unroll
        for (int o = 16; o > 0; o >>= 1) {
            m0 = fmaxf(m0, __shfl_xor_sync(0xffffffffu, m0, o));
            m1 = fmaxf(m1, __shfl_xor_sync(0xffffffffu, m1, o));
        }
        float z0 = 0.f, z1 = 0.f;
        for (int j = tid; j < deg; j += 32) {
            int s = g_esrc[start + j];
            float e0 = lrelu(g_el[s * 2 + 0] + er0, 0.2f);
            float e1 = lrelu(g_el[s * 2 + 1] + er1, 0.2f);
            z0 += expf(e0 - m0);
            z1 += expf(e1 - m1);
        }
#pragma unroll
        for (int o = 16; o > 0; o >>= 1) {
            z0 += __shfl_xor_sync(0xffffffffu, z0, o);
            z1 += __shfl_xor_sync(0xffffffffu, z1, o);
        }
        if (tid == 0) {
            s_m0 = m0; s_m1 = m1;
            s_i0 = (deg > 0) ? 1.f / z0 : 0.f;
            s_i1 = (deg > 0) ? 1.f / z1 : 0.f;
        }
    }
    __syncthreads();
    float m0 = s_m0, m1 = s_m1, i0 = s_i0, i1 = s_i1;

    // pair index p covers channels (2p, 2p+1); d pairs total (HD/2 == d)
    int dh = d >> 1;  // pairs in head 0
    float2 acc2[2];
    acc2[0] = make_float2(0.f, 0.f);
    acc2[1] = make_float2(0.f, 0.f);

    for (int c0 = 0; c0 < deg; c0 += 32) {
        int cn = min(32, deg - c0);
        if (tid < cn) {
            int s = g_esrc[start + c0 + tid];
            s_src[tid] = s;
            float e0 = lrelu(g_el[s * 2 + 0] + er0, 0.2f);
            float e1 = lrelu(g_el[s * 2 + 1] + er1, 0.2f);
            s_w[tid][0] = expf(e0 - m0) * i0;
            s_w[tid][1] = expf(e1 - m1) * i1;
        }
        __syncthreads();
        for (int j = 0; j < cn; j++) {
            const __half2* hrow = (const __half2*)(g_h + (size_t)s_src[j] * HD);
            float w0 = s_w[j][0], w1 = s_w[j][1];
#pragma unroll
            for (int k = 0; k < 2; k++) {
                int p = tid + k * 256;
                if (p < d) {
                    float w = (p < dh) ? w0 : w1;
                    float2 v = __half22float2(__ldg(hrow + p));
                    acc2[k].x = fmaf(w, v.x, acc2[k].x);
                    acc2[k].y = fmaf(w, v.y, acc2[k].y);
                }
            }
        }
        __syncthreads();
    }
#pragma unroll
    for (int k = 0; k < 2; k++) {
        int p = tid + k * 256;
        if (p < d) {
            float2 r = ((const float2*)(g_r + (size_t)n * HD))[p];
            float2 o = make_float2(acc2[k].x + r.x, acc2[k].y + r.y);
            ((float2*)(g_x + (size_t)n * HD))[p] = o;
        }
    }
}

// ---------------- GraphNorm stats ----------------
__global__ void __launch_bounds__(128) k_colstats(int d) {
    int r0 = blockIdx.x * 32;
    int c4 = threadIdx.x;
    int q = d >> 2;
    if (c4 >= q) return;
    float a0 = 0.f, a1 = 0.f, a2 = 0.f, a3 = 0.f;
    float b0 = 0.f, b1 = 0.f, b2 = 0.f, b3 = 0.f;
    for (int r = 0; r < 32; r++) {
        const float4* row = (const float4*)(g_x + (size_t)(r0 + r) * d);
        float4 v = row[c4];
        a0 += v.x; b0 += v.x * v.x;
        a1 += v.y; b1 += v.y * v.y;
        a2 += v.z; b2 += v.z * v.z;
        a3 += v.w; b3 += v.w * v.w;
    }
    int c = c4 * 4;
    atomicAdd(&g_s1[c + 0], a0); atomicAdd(&g_s2[c + 0], b0);
    atomicAdd(&g_s1[c + 1], a1); atomicAdd(&g_s2[c + 1], b1);
    atomicAdd(&g_s1[c + 2], a2); atomicAdd(&g_s2[c + 2], b2);
    atomicAdd(&g_s1[c + 3], a3); atomicAdd(&g_s2[c + 3], b3);
}

__global__ void k_finstats(const float* __restrict__ gamma, const float* __restrict__ beta,
                           const float* __restrict__ alpha, int d) {
    int c = blockIdx.x * blockDim.x + threadIdx.x;
    if (c >= d) return;
    const float inv_nh = 1.f / (float)(NN * HH);
    float mean = g_s1[c] * inv_nh;
    float ex2 = g_s2[c] * inv_nh;
    float a = alpha[c];
    float var = ex2 - 2.f * a * mean * mean + a * a * mean * mean;
    float inv = rsqrtf(var + 1e-5f);
    float sc = gamma[c] * inv;
    g_scale[c] = sc;
    g_bias[c] = beta[c] - sc * a * mean;
}

// ---------------- normalize + lrelu + head-mean partials (fp16 next-layer input) ------
__global__ void k_norm(const int* __restrict__ gid, int d, int off, int writeY) {
    int nb = blockIdx.x * 16;
    int g = gid[nb];
    int c0 = threadIdx.x, c1 = threadIdx.x + 256;
    float acc0 = 0.f, acc1 = 0.f;
    float sc0 = 0.f, bi0 = 0.f, sc1 = 0.f, bi1 = 0.f;
    if (c0 < d) { sc0 = g_scale[c0]; bi0 = g_bias[c0]; }
    if (c1 < d) { sc1 = g_scale[c1]; bi1 = g_bias[c1]; }
    for (int i = 0; i < 16; i++) {
        size_t base = (size_t)(nb + i) * 2 * d;
        if (c0 < d) {
            float y0 = lrelu(g_x[base + c0] * sc0 + bi0, 0.01f);
            float y1 = lrelu(g_x[base + d + c0] * sc0 + bi0, 0.01f);
            if (writeY) {
                g_abf[base + c0] = __float2half(y0);
                g_abf[base + d + c0] = __float2half(y1);
            }
            acc0 += y0 + y1;
        }
        if (c1 < d) {
            float y0 = lrelu(g_x[base + c1] * sc1 + bi1, 0.01f);
            float y1 = lrelu(g_x[base + d + c1] * sc1 + bi1, 0.01f);
            if (writeY) {
                g_abf[base + c1] = __float2half(y0);
                g_abf[base + d + c1] = __float2half(y1);
            }
            acc1 += y0 + y1;
        }
    }
    if (c0 < d) atomicAdd(&g_parts[g * OUTC + off + c0], acc0);
    if (c1 < d) atomicAdd(&g_parts[g * OUTC + off + c1], acc1);
}

// ---------------- final ----------------
__global__ void k_final(float* __restrict__ out) {
    int i = blockIdx.x * blockDim.x + threadIdx.x;
    if (i < BB * OUTC) {
        int b = i / OUTC;
        float v = g_parts[i] / (2.f * (float)g_counts[b]);
        out[i] = lrelu(v, 0.01f);
    }
}

// ---------------- launch ----------------
extern "C" void kernel_launch(void* const* d_in, const int* in_sizes, int n_in,
                              void* d_out, int out_size) {
    const float* nf = (const float*)d_in[0];
    const float* W[3]  = {(const float*)d_in[1],  (const float*)d_in[8],  (const float*)d_in[15]};
    const float* AL[3] = {(const float*)d_in[2],  (const float*)d_in[9],  (const float*)d_in[16]};
    const float* AR[3] = {(const float*)d_in[3],  (const float*)d_in[10], (const float*)d_in[17]};
    const float* RW[3] = {(const float*)d_in[4],  (const float*)d_in[11], (const float*)d_in[18]};
    const float* GA[3] = {(const float*)d_in[5],  (const float*)d_in[12], (const float*)d_in[19]};
    const float* BE[3] = {(const float*)d_in[6],  (const float*)d_in[13], (const float*)d_in[20]};
    const float* AP[3] = {(const float*)d_in[7],  (const float*)d_in[14], (const float*)d_in[21]};
    const int* src = (const int*)d_in[22];
    const int* dst = (const int*)d_in[23];
    const int* gid = (const int*)d_in[24];
    float* out = (float*)d_out;

    const int dims[3] = {128, 256, 512};
    const int offs[3] = {0, 128, 384};

    k_zero<<<(NN + 255) / 256, 256>>>();
    k_build<<<EE / 256, 256>>>(dst, gid);
    k_scan1<<<64, 256>>>();
    k_scan2<<<1, 64>>>();
    k_scan3<<<NN / 256, 256>>>();

    k_cvtA<<<(NN * 128 / 4 + 255) / 256, 256>>>(nf, NN * 128 / 4);
    {
        dim3 tg(32, 8);
        dim3 wg(dims[0] * 2 / 32, dims[0] / 32, 2);
        k_cvtW<<<wg, tg>>>(W[0], RW[0], dims[0], dims[0] * 2);
        dim3 gg(dims[0] * 2 / 128, NN / 128, 2);
        k_mma<<<gg, 256>>>(dims[0], dims[0] * 2);
    }
    k_scatter<<<EE / 256, 256>>>(src, dst);

    for (int l = 0; l < 3; l++) {
        int d = dims[l], HD = 2 * d;
        if (l > 0) {
            dim3 tg(32, 8);
            dim3 wg(HD / 32, d / 32, 2);
            k_cvtW<<<wg, tg>>>(W[l], RW[l], d, HD);
            dim3 gg(HD / 128, NN / 128, 2);
            k_mma<<<gg, 256>>>(d, HD);
        }
        k_attn<<<(NN * HH * 32) / 256, 256>>>(AL[l], AR[l], d);
        k_agg<<<NN, 256>>>(d);
        k_colstats<<<(NN * HH) / 32, 128>>>(d);
        k_finstats<<<(d + 255) / 256, 256>>>(GA[l], BE[l], AP[l], d);
        k_norm<<<NN / 16, 256>>>(gid, d, offs[l], (l < 2) ? 1 : 0);
    }
    k_final<<<(BB * OUTC + 255) / 256, 256>>>(out);
}

// round 15
// speedup vs baseline: 1.3939x; 1.1150x over previous
#include <cuda_runtime.h>
#include <cuda_fp16.h>
#include <math.h>
#include <stdint.h>

#define NN 16384
#define EE 131072
#define BB 16
#define HH 2
#define MAXD 512
#define MAXHD 1024
#define OUTC 896

// ---------------- scratch (device globals; no allocation) ----------------
__device__ __half g_x[(size_t)NN * MAXHD];       // fp16 GAT output (agg result)
__device__ __half g_abf[(size_t)NN * MAXD];      // fp16 GEMM input (A)
__device__ __half g_wTa[(size_t)MAXD * MAXHD];   // fp16 W transposed [N][K]
__device__ __half g_wTb[(size_t)MAXD * MAXHD];   // fp16 rW transposed [N][K]
__device__ __half g_h[(size_t)NN * MAXHD];       // fp16 h = x @ W
__device__ __half g_r[(size_t)NN * MAXHD];       // fp16 residual
__device__ float g_el[NN * HH];
__device__ float g_er[NN * HH];
__device__ int   g_indptr[NN + 1];
__device__ int   g_cnt[NN];
__device__ int   g_cur[NN];
__device__ int   g_esrc[EE];
__device__ int   g_bsum[64];
__device__ int   g_boff[64];
__device__ float g_s1[MAXD];
__device__ float g_s2[MAXD];
__device__ float g_scale[MAXD];
__device__ float g_bias[MAXD];
__device__ float g_parts[BB * OUTC];
__device__ int   g_counts[BB];

__device__ __forceinline__ float lrelu(float v, float s) { return v > 0.f ? v : s * v; }

__device__ __forceinline__ void cp_async16(uint32_t saddr, const void* gptr) {
    asm volatile("cp.async.cg.shared.global [%0], [%1], 16;" :: "r"(saddr), "l"(gptr));
}
__device__ __forceinline__ void cp_commit() { asm volatile("cp.async.commit_group;"); }

// ---------------- front ----------------
__global__ void k_zero() {
    int i = blockIdx.x * blockDim.x + threadIdx.x;
    if (i < BB * OUTC) g_parts[i] = 0.f;
    if (i < BB) g_counts[i] = 0;
    if (i < NN) g_cnt[i] = 0;
}

__global__ void k_build(const int* __restrict__ dst, const int* __restrict__ gid) {
    int i = blockIdx.x * blockDim.x + threadIdx.x;
    if (i < EE) atomicAdd(&g_cnt[dst[i]], 1);
    if (i < NN) atomicAdd(&g_counts[gid[i]], 1);
}

__global__ void k_scan1() {
    __shared__ int sm[256];
    int tid = threadIdx.x;
    int i = blockIdx.x * 256 + tid;
    int v = g_cnt[i];
    sm[tid] = v;
    __syncthreads();
    for (int off = 1; off < 256; off <<= 1) {
        int t = (tid >= off) ? sm[tid - off] : 0;
        __syncthreads();
        sm[tid] += t;
        __syncthreads();
    }
    g_indptr[i] = sm[tid] - v;
    g_cur[i] = 0;
    if (tid == 255) g_bsum[blockIdx.x] = sm[255];
}

__global__ void k_scan2() {
    __shared__ int sm[64];
    int tid = threadIdx.x;
    int v = g_bsum[tid];
    sm[tid] = v;
    __syncthreads();
    for (int off = 1; off < 64; off <<= 1) {
        int t = (tid >= off) ? sm[tid - off] : 0;
        __syncthreads();
        sm[tid] += t;
        __syncthreads();
    }
    g_boff[tid] = sm[tid] - v;
    if (tid == 63) g_indptr[NN] = sm[63];
}

__global__ void k_scan3() {
    int i = blockIdx.x * blockDim.x + threadIdx.x;
    if (i < NN) g_indptr[i] += g_boff[i >> 8];
}

__global__ void k_scatter(const int* __restrict__ src, const int* __restrict__ dst) {
    int i = blockIdx.x * blockDim.x + threadIdx.x;
    if (i < EE) {
        int d = dst[i];
        int p = g_indptr[d] + atomicAdd(&g_cur[d], 1);
        g_esrc[p] = src[i];
    }
}

// ---------------- fp32 -> fp16 conversions ----------------
__global__ void k_cvtA(const float* __restrict__ src, int n4) {
    int i = blockIdx.x * blockDim.x + threadIdx.x;
    if (i < n4) {
        float4 v = reinterpret_cast<const float4*>(src)[i];
        __half2* o = reinterpret_cast<__half2*>(g_abf);
        o[2 * i + 0] = __floats2half2_rn(v.x, v.y);
        o[2 * i + 1] = __floats2half2_rn(v.z, v.w);
    }
}

__global__ void k_cvtW(const float* __restrict__ W, const float* __restrict__ R,
                       int K, int N) {
    __shared__ float t[32][33];
    const float* S = blockIdx.z ? R : W;
    __half* D = blockIdx.z ? g_wTb : g_wTa;
    int n0 = blockIdx.x * 32, k0 = blockIdx.y * 32;
    for (int r = threadIdx.y; r < 32; r += 8)
        t[r][threadIdx.x] = S[(size_t)(k0 + r) * N + n0 + threadIdx.x];
    __syncthreads();
    for (int r = threadIdx.y; r < 32; r += 8)
        D[(size_t)(n0 + r) * K + k0 + threadIdx.x] = __float2half(t[threadIdx.x][r]);
}

// ---------------- FP16 tensor-core GEMM (m16n8k16), 3-stage cp.async ----------------
// Block 128x128, BK=16. z=0: C=g_h, z=1: C=g_r (both fp16).
__global__ void __launch_bounds__(256) k_mma(int K, int Nc) {
    __shared__ __align__(16) __half As[3][128][24];
    __shared__ __align__(16) __half Bs[3][128][24];

    const __half* A = g_abf;
    const __half* BT = blockIdx.z ? g_wTb : g_wTa;
    __half* C = blockIdx.z ? g_r : g_h;

    int tid = threadIdx.x;
    int lane = tid & 31;
    int warp = tid >> 5;
    int wm = (warp >> 1) * 32;
    int wn = (warp & 1) * 64;
    int rowT = blockIdx.y * 128;
    int colT = blockIdx.x * 128;
    int gr = lane >> 2;
    int tg = lane & 3;

    int ldRow = tid >> 1;
    int ldChunk = (tid & 1) * 8;

    float acc[2][8][4];
#pragma unroll
    for (int i = 0; i < 2; i++)
#pragma unroll
        for (int j = 0; j < 8; j++)
#pragma unroll
            for (int c = 0; c < 4; c++) acc[i][j][c] = 0.f;

    int iters = K >> 4;

    auto load_stage = [&](int s, int kt) {
        uint32_t sa = (uint32_t)__cvta_generic_to_shared(&As[s][ldRow][ldChunk]);
        cp_async16(sa, A + (size_t)(rowT + ldRow) * K + kt + ldChunk);
        uint32_t sb = (uint32_t)__cvta_generic_to_shared(&Bs[s][ldRow][ldChunk]);
        cp_async16(sb, BT + (size_t)(colT + ldRow) * K + kt + ldChunk);
    };

    load_stage(0, 0);
    cp_commit();
    load_stage(1, 16);
    cp_commit();

    for (int it = 0; it < iters; it++) {
        if (it + 1 < iters) asm volatile("cp.async.wait_group 1;");
        else                asm volatile("cp.async.wait_group 0;");
        __syncthreads();

        if (it + 2 < iters) {
            load_stage((it + 2) % 3, (it + 2) << 4);
            cp_commit();
        }

        int cur = it % 3;
        uint32_t af[2][4];
#pragma unroll
        for (int i = 0; i < 2; i++) {
            int m0 = wm + i * 16 + gr;
            af[i][0] = *reinterpret_cast<const uint32_t*>(&As[cur][m0][2 * tg]);
            af[i][1] = *reinterpret_cast<const uint32_t*>(&As[cur][m0 + 8][2 * tg]);
            af[i][2] = *reinterpret_cast<const uint32_t*>(&As[cur][m0][2 * tg + 8]);
            af[i][3] = *reinterpret_cast<const uint32_t*>(&As[cur][m0 + 8][2 * tg + 8]);
        }
        uint32_t bf[8][2];
#pragma unroll
        for (int j = 0; j < 8; j++) {
            int n0 = wn + j * 8 + gr;
            bf[j][0] = *reinterpret_cast<const uint32_t*>(&Bs[cur][n0][2 * tg]);
            bf[j][1] = *reinterpret_cast<const uint32_t*>(&Bs[cur][n0][2 * tg + 8]);
        }
#pragma unroll
        for (int i = 0; i < 2; i++)
#pragma unroll
            for (int j = 0; j < 8; j++) {
                asm volatile(
                    "mma.sync.aligned.m16n8k16.row.col.f32.f16.f16.f32 "
                    "{%0,%1,%2,%3},{%4,%5,%6,%7},{%8,%9},{%0,%1,%2,%3};"
                    : "+f"(acc[i][j][0]), "+f"(acc[i][j][1]),
                      "+f"(acc[i][j][2]), "+f"(acc[i][j][3])
                    : "r"(af[i][0]), "r"(af[i][1]), "r"(af[i][2]), "r"(af[i][3]),
                      "r"(bf[j][0]), "r"(bf[j][1]));
            }
        __syncthreads();
    }

#pragma unroll
    for (int i = 0; i < 2; i++) {
        int r0 = rowT + wm + i * 16 + gr;
#pragma unroll
        for (int j = 0; j < 8; j++) {
            int ccol = colT + wn + j * 8 + tg * 2;
            *reinterpret_cast<__half2*>(C + (size_t)r0 * Nc + ccol) =
                __floats2half2_rn(acc[i][j][0], acc[i][j][1]);
            *reinterpret_cast<__half2*>(C + (size_t)(r0 + 8) * Nc + ccol) =
                __floats2half2_rn(acc[i][j][2], acc[i][j][3]);
        }
    }
}

// ---------------- attention projections el/er from fp16 h (+ zero s1/s2) -------------
__global__ void k_attn(const float* __restrict__ al, const float* __restrict__ ar, int d) {
    if (blockIdx.x == 0) {
        g_s1[threadIdx.x] = 0.f;
        g_s1[threadIdx.x + 256] = 0.f;
        g_s2[threadIdx.x] = 0.f;
        g_s2[threadIdx.x + 256] = 0.f;
    }
    int gw = (blockIdx.x * blockDim.x + threadIdx.x) >> 5;
    int lane = threadIdx.x & 31;
    if (gw >= NN * HH) return;
    int n = gw >> 1, hd = gw & 1;
    const __half2* hr = (const __half2*)(g_h + (size_t)n * (2 * d) + hd * d);
    const float2* av = (const float2*)(al + hd * d);
    const float2* bv = (const float2*)(ar + hd * d);
    int q = d >> 1;
    float sl = 0.f, sr = 0.f;
    for (int c = lane; c < q; c += 32) {
        float2 v = __half22float2(hr[c]);
        float2 a = av[c], b = bv[c];
        sl += v.x * a.x + v.y * a.y;
        sr += v.x * b.x + v.y * b.y;
    }
#pragma unroll
    for (int o = 16; o > 0; o >>= 1) {
        sl += __shfl_down_sync(0xffffffffu, sl, o);
        sr += __shfl_down_sync(0xffffffffu, sr, o);
    }
    if (lane == 0) { g_el[gw] = sl; g_er[gw] = sr; }
}

// ---------------- per-dst softmax + fp16 gather aggregation (+ fp16 residual) ---------
__global__ void __launch_bounds__(256) k_agg(int d) {
    const int HD = 2 * d;
    int n = blockIdx.x;
    int tid = threadIdx.x;
    int start = g_indptr[n];
    int deg = g_indptr[n + 1] - start;
    __shared__ float s_m0, s_m1, s_i0, s_i1;
    __shared__ int s_src[32];
    __shared__ float s_w[32][2];
    float er0 = g_er[n * 2 + 0];
    float er1 = g_er[n * 2 + 1];

    if (tid < 32) {
        float m0 = -1e30f, m1 = -1e30f;
        for (int j = tid; j < deg; j += 32) {
            int s = g_esrc[start + j];
            float e0 = lrelu(g_el[s * 2 + 0] + er0, 0.2f);
            float e1 = lrelu(g_el[s * 2 + 1] + er1, 0.2f);
            m0 = fmaxf(m0, e0); m1 = fmaxf(m1, e1);
        }
#pragma unroll
        for (int o = 16; o > 0; o >>= 1) {
            m0 = fmaxf(m0, __shfl_xor_sync(0xffffffffu, m0, o));
            m1 = fmaxf(m1, __shfl_xor_sync(0xffffffffu, m1, o));
        }
        float z0 = 0.f, z1 = 0.f;
        for (int j = tid; j < deg; j += 32) {
            int s = g_esrc[start + j];
            float e0 = lrelu(g_el[s * 2 + 0] + er0, 0.2f);
            float e1 = lrelu(g_el[s * 2 + 1] + er1, 0.2f);
            z0 += expf(e0 - m0);
            z1 += expf(e1 - m1);
        }
#pragma unroll
        for (int o = 16; o > 0; o >>= 1) {
            z0 += __shfl_xor_sync(0xffffffffu, z0, o);
            z1 += __shfl_xor_sync(0xffffffffu, z1, o);
        }
        if (tid == 0) {
            s_m0 = m0; s_m1 = m1;
            s_i0 = (deg > 0) ? 1.f / z0 : 0.f;
            s_i1 = (deg > 0) ? 1.f / z1 : 0.f;
        }
    }
    __syncthreads();
    float m0 = s_m0, m1 = s_m1, i0 = s_i0, i1 = s_i1;

    int dh = d >> 1;  // pairs in head 0 (d pairs total per row)
    float2 acc2[2];
    acc2[0] = make_float2(0.f, 0.f);
    acc2[1] = make_float2(0.f, 0.f);

    for (int c0 = 0; c0 < deg; c0 += 32) {
        int cn = min(32, deg - c0);
        if (tid < cn) {
            int s = g_esrc[start + c0 + tid];
            s_src[tid] = s;
            float e0 = lrelu(g_el[s * 2 + 0] + er0, 0.2f);
            float e1 = lrelu(g_el[s * 2 + 1] + er1, 0.2f);
            s_w[tid][0] = expf(e0 - m0) * i0;
            s_w[tid][1] = expf(e1 - m1) * i1;
        }
        __syncthreads();
        for (int j = 0; j < cn; j++) {
            const __half2* hrow = (const __half2*)(g_h + (size_t)s_src[j] * HD);
            float w0 = s_w[j][0], w1 = s_w[j][1];
#pragma unroll
            for (int k = 0; k < 2; k++) {
                int p = tid + k * 256;
                if (p < d) {
                    float w = (p < dh) ? w0 : w1;
                    float2 v = __half22float2(__ldg(hrow + p));
                    acc2[k].x = fmaf(w, v.x, acc2[k].x);
                    acc2[k].y = fmaf(w, v.y, acc2[k].y);
                }
            }
        }
        __syncthreads();
    }
#pragma unroll
    for (int k = 0; k < 2; k++) {
        int p = tid + k * 256;
        if (p < d) {
            float2 r = __half22float2(((const __half2*)g_r)[(size_t)n * d + p]);
            ((__half2*)g_x)[(size_t)n * d + p] =
                __floats2half2_rn(acc2[k].x + r.x, acc2[k].y + r.y);
        }
    }
}

// ---------------- GraphNorm stats (fp16 x, pair-wise) ----------------
__global__ void __launch_bounds__(256) k_colstats(int d) {
    int r0 = blockIdx.x * 32;     // rows of [NN*HH, d] view
    int p = threadIdx.x;          // pair index
    int q = d >> 1;
    if (p >= q) return;
    float a0 = 0.f, b0 = 0.f, a1 = 0.f, b1 = 0.f;
    for (int r = 0; r < 32; r++) {
        const __half2* row = (const __half2*)g_x + (size_t)(r0 + r) * q;
        float2 v = __half22float2(row[p]);
        a0 += v.x; b0 += v.x * v.x;
        a1 += v.y; b1 += v.y * v.y;
    }
    int c = p * 2;
    atomicAdd(&g_s1[c + 0], a0); atomicAdd(&g_s2[c + 0], b0);
    atomicAdd(&g_s1[c + 1], a1); atomicAdd(&g_s2[c + 1], b1);
}

__global__ void k_finstats(const float* __restrict__ gamma, const float* __restrict__ beta,
                           const float* __restrict__ alpha, int d) {
    int c = blockIdx.x * blockDim.x + threadIdx.x;
    if (c >= d) return;
    const float inv_nh = 1.f / (float)(NN * HH);
    float mean = g_s1[c] * inv_nh;
    float ex2 = g_s2[c] * inv_nh;
    float a = alpha[c];
    float var = ex2 - 2.f * a * mean * mean + a * a * mean * mean;
    float inv = rsqrtf(var + 1e-5f);
    float sc = gamma[c] * inv;
    g_scale[c] = sc;
    g_bias[c] = beta[c] - sc * a * mean;
}

// ---------------- normalize + lrelu + head-mean partials (fp16 in/out, pair-wise) -----
__global__ void k_norm(const int* __restrict__ gid, int d, int off, int writeY) {
    int nb = blockIdx.x * 16;
    int g = gid[nb];
    int tid = threadIdx.x;
    float2 sc[2], bi[2], acc[2];
    int w[2], act[2];
#pragma unroll
    for (int k = 0; k < 2; k++) {
        int p = tid + k * 256;
        act[k] = (p < d);
        acc[k] = make_float2(0.f, 0.f);
        if (act[k]) {
            int ch = 2 * p;
            int ww = (ch < d) ? ch : ch - d;    // within-head channel (pairs never straddle heads; d even)
            w[k] = ww;
            sc[k] = make_float2(g_scale[ww], g_scale[ww + 1]);
            bi[k] = make_float2(g_bias[ww], g_bias[ww + 1]);
        }
    }
    for (int i = 0; i < 16; i++) {
        size_t base2 = (size_t)(nb + i) * d;   // row in half2 units (HD/2 == d pairs)
        const __half2* xr = (const __half2*)g_x + base2;
        __half2* yr = (__half2*)g_abf + base2;
#pragma unroll
        for (int k = 0; k < 2; k++) {
            int p = tid + k * 256;
            if (act[k]) {
                float2 v = __half22float2(xr[p]);
                float y0 = lrelu(v.x * sc[k].x + bi[k].x, 0.01f);
                float y1 = lrelu(v.y * sc[k].y + bi[k].y, 0.01f);
                if (writeY) yr[p] = __floats2half2_rn(y0, y1);
                acc[k].x += y0;
                acc[k].y += y1;
            }
        }
    }
#pragma unroll
    for (int k = 0; k < 2; k++) {
        if (act[k]) {
            atomicAdd(&g_parts[g * OUTC + off + w[k] + 0], acc[k].x);
            atomicAdd(&g_parts[g * OUTC + off + w[k] + 1], acc[k].y);
        }
    }
}

// ---------------- final ----------------
__global__ void k_final(float* __restrict__ out) {
    int i = blockIdx.x * blockDim.x + threadIdx.x;
    if (i < BB * OUTC) {
        int b = i / OUTC;
        float v = g_parts[i] / (2.f * (float)g_counts[b]);
        out[i] = lrelu(v, 0.01f);
    }
}

// ---------------- launch ----------------
extern "C" void kernel_launch(void* const* d_in, const int* in_sizes, int n_in,
                              void* d_out, int out_size) {
    const float* nf = (const float*)d_in[0];
    const float* W[3]  = {(const float*)d_in[1],  (const float*)d_in[8],  (const float*)d_in[15]};
    const float* AL[3] = {(const float*)d_in[2],  (const float*)d_in[9],  (const float*)d_in[16]};
    const float* AR[3] = {(const float*)d_in[3],  (const float*)d_in[10], (const float*)d_in[17]};
    const float* RW[3] = {(const float*)d_in[4],  (const float*)d_in[11], (const float*)d_in[18]};
    const float* GA[3] = {(const float*)d_in[5],  (const float*)d_in[12], (const float*)d_in[19]};
    const float* BE[3] = {(const float*)d_in[6],  (const float*)d_in[13], (const float*)d_in[20]};
    const float* AP[3] = {(const float*)d_in[7],  (const float*)d_in[14], (const float*)d_in[21]};
    const int* src = (const int*)d_in[22];
    const int* dst = (const int*)d_in[23];
    const int* gid = (const int*)d_in[24];
    float* out = (float*)d_out;

    const int dims[3] = {128, 256, 512};
    const int offs[3] = {0, 128, 384};

    k_zero<<<(NN + 255) / 256, 256>>>();
    k_build<<<EE / 256, 256>>>(dst, gid);
    k_scan1<<<64, 256>>>();
    k_scan2<<<1, 64>>>();
    k_scan3<<<NN / 256, 256>>>();

    k_cvtA<<<(NN * 128 / 4 + 255) / 256, 256>>>(nf, NN * 128 / 4);
    {
        dim3 tg(32, 8);
        dim3 wg(dims[0] * 2 / 32, dims[0] / 32, 2);
        k_cvtW<<<wg, tg>>>(W[0], RW[0], dims[0], dims[0] * 2);
        dim3 gg(dims[0] * 2 / 128, NN / 128, 2);
        k_mma<<<gg, 256>>>(dims[0], dims[0] * 2);
    }
    k_scatter<<<EE / 256, 256>>>(src, dst);

    for (int l = 0; l < 3; l++) {
        int d = dims[l], HD = 2 * d;
        if (l > 0) {
            dim3 tg(32, 8);
            dim3 wg(HD / 32, d / 32, 2);
            k_cvtW<<<wg, tg>>>(W[l], RW[l], d, HD);
            dim3 gg(HD / 128, NN / 128, 2);
            k_mma<<<gg, 256>>>(d, HD);
        }
        k_attn<<<(NN * HH * 32) / 256, 256>>>(AL[l], AR[l], d);
        k_agg<<<NN, 256>>>(d);
        k_colstats<<<(NN * HH) / 32, 256>>>(d);
        k_finstats<<<(d + 255) / 256, 256>>>(GA[l], BE[l], AP[l], d);
        k_norm<<<NN / 16, 256>>>(gid, d, offs[l], (l < 2) ? 1 : 0);
    }
    k_final<<<(BB * OUTC + 255) / 256, 256>>>(out);
}

// round 16
// speedup vs baseline: 1.4530x; 1.0424x over previous
#include <cuda_runtime.h>
#include <cuda_fp16.h>
#include <math.h>
#include <stdint.h>

#define NN 16384
#define EE 131072
#define BB 16
#define HH 2
#define MAXD 512
#define MAXHD 1024
#define OUTC 896

// ---------------- scratch (device globals; no allocation) ----------------
__device__ __half g_x[(size_t)NN * MAXHD];       // fp16 GAT output (agg result)
__device__ __half g_abf[(size_t)NN * MAXD];      // fp16 GEMM input (A)
__device__ __half g_wTa[(size_t)MAXD * MAXHD];   // fp16 W transposed [N][K]
__device__ __half g_wTb[(size_t)MAXD * MAXHD];   // fp16 rW transposed [N][K]
__device__ __half g_h[(size_t)NN * MAXHD];       // fp16 h = x @ W
__device__ __half g_r[(size_t)NN * MAXHD];       // fp16 residual
__device__ float g_el[NN * HH];
__device__ float g_er[NN * HH];
__device__ int   g_indptr[NN + 1];
__device__ int   g_cnt[NN];
__device__ int   g_cur[NN];
__device__ int   g_esrc[EE];
__device__ int   g_bsum[64];
__device__ int   g_boff[64];
__device__ float g_s1[MAXD];
__device__ float g_s2[MAXD];
__device__ float g_parts[BB * OUTC];
__device__ int   g_counts[BB];

__device__ __forceinline__ float lrelu(float v, float s) { return v > 0.f ? v : s * v; }

__device__ __forceinline__ void cp_async16(uint32_t saddr, const void* gptr) {
    asm volatile("cp.async.cg.shared.global [%0], [%1], 16;" :: "r"(saddr), "l"(gptr));
}
__device__ __forceinline__ void cp_commit() { asm volatile("cp.async.commit_group;"); }

// ---------------- front ----------------
__global__ void k_zero() {
    int i = blockIdx.x * blockDim.x + threadIdx.x;
    if (i < BB * OUTC) g_parts[i] = 0.f;
    if (i < BB) g_counts[i] = 0;
    if (i < NN) g_cnt[i] = 0;
}

__global__ void k_build(const int* __restrict__ dst, const int* __restrict__ gid) {
    int i = blockIdx.x * blockDim.x + threadIdx.x;
    if (i < EE) atomicAdd(&g_cnt[dst[i]], 1);
    if (i < NN) atomicAdd(&g_counts[gid[i]], 1);
}

__global__ void k_scan1() {
    __shared__ int sm[256];
    int tid = threadIdx.x;
    int i = blockIdx.x * 256 + tid;
    int v = g_cnt[i];
    sm[tid] = v;
    __syncthreads();
    for (int off = 1; off < 256; off <<= 1) {
        int t = (tid >= off) ? sm[tid - off] : 0;
        __syncthreads();
        sm[tid] += t;
        __syncthreads();
    }
    g_indptr[i] = sm[tid] - v;
    g_cur[i] = 0;
    if (tid == 255) g_bsum[blockIdx.x] = sm[255];
}

__global__ void k_scan2() {
    __shared__ int sm[64];
    int tid = threadIdx.x;
    int v = g_bsum[tid];
    sm[tid] = v;
    __syncthreads();
    for (int off = 1; off < 64; off <<= 1) {
        int t = (tid >= off) ? sm[tid - off] : 0;
        __syncthreads();
        sm[tid] += t;
        __syncthreads();
    }
    g_boff[tid] = sm[tid] - v;
    if (tid == 63) g_indptr[NN] = sm[63];
}

__global__ void k_scan3() {
    int i = blockIdx.x * blockDim.x + threadIdx.x;
    if (i < NN) g_indptr[i] += g_boff[i >> 8];
}

__global__ void k_scatter(const int* __restrict__ src, const int* __restrict__ dst) {
    int i = blockIdx.x * blockDim.x + threadIdx.x;
    if (i < EE) {
        int d = dst[i];
        int p = g_indptr[d] + atomicAdd(&g_cur[d], 1);
        g_esrc[p] = src[i];
    }
}

// ---------------- fp32 -> fp16 conversions ----------------
__global__ void k_cvtA(const float* __restrict__ src, int n4) {
    int i = blockIdx.x * blockDim.x + threadIdx.x;
    if (i < n4) {
        float4 v = reinterpret_cast<const float4*>(src)[i];
        __half2* o = reinterpret_cast<__half2*>(g_abf);
        o[2 * i + 0] = __floats2half2_rn(v.x, v.y);
        o[2 * i + 1] = __floats2half2_rn(v.z, v.w);
    }
}

// transpose+convert AND zero per-layer accumulators (el/er/s1/s2)
__global__ void k_cvtW(const float* __restrict__ W, const float* __restrict__ R,
                       int K, int N) {
    // per-layer zeroing via grid-stride loop
    int total = gridDim.x * gridDim.y * gridDim.z * 256;
    int lin = (((blockIdx.z * gridDim.y + blockIdx.y) * gridDim.x + blockIdx.x) * 256)
              + threadIdx.y * 32 + threadIdx.x;
    for (int t = lin; t < NN * HH; t += total) { g_el[t] = 0.f; g_er[t] = 0.f; }
    if (lin < MAXD) { g_s1[lin] = 0.f; g_s2[lin] = 0.f; }

    __shared__ float tbuf[32][33];
    const float* S = blockIdx.z ? R : W;
    __half* D = blockIdx.z ? g_wTb : g_wTa;
    int n0 = blockIdx.x * 32, k0 = blockIdx.y * 32;
    for (int r = threadIdx.y; r < 32; r += 8)
        tbuf[r][threadIdx.x] = S[(size_t)(k0 + r) * N + n0 + threadIdx.x];
    __syncthreads();
    for (int r = threadIdx.y; r < 32; r += 8)
        D[(size_t)(n0 + r) * K + k0 + threadIdx.x] = __float2half(tbuf[threadIdx.x][r]);
}

// ---------------- FP16 tensor-core GEMM (m16n8k16) + fused attn projections ----------
// Block 128x128, BK=16, 3-stage cp.async. z=0: C=g_h + el/er partials; z=1: C=g_r.
__global__ void __launch_bounds__(256) k_mma(const float* __restrict__ al,
                                             const float* __restrict__ ar,
                                             int K, int Nc) {
    __shared__ __align__(16) __half As[3][128][24];
    __shared__ __align__(16) __half Bs[3][128][24];

    const __half* A = g_abf;
    const __half* BT = blockIdx.z ? g_wTb : g_wTa;
    __half* C = blockIdx.z ? g_r : g_h;

    int tid = threadIdx.x;
    int lane = tid & 31;
    int warp = tid >> 5;
    int wm = (warp >> 1) * 32;
    int wn = (warp & 1) * 64;
    int rowT = blockIdx.y * 128;
    int colT = blockIdx.x * 128;
    int gr = lane >> 2;
    int tg = lane & 3;

    int ldRow = tid >> 1;
    int ldChunk = (tid & 1) * 8;

    float acc[2][8][4];
#pragma unroll
    for (int i = 0; i < 2; i++)
#pragma unroll
        for (int j = 0; j < 8; j++)
#pragma unroll
            for (int c = 0; c < 4; c++) acc[i][j][c] = 0.f;

    int iters = K >> 4;

    auto load_stage = [&](int s, int kt) {
        uint32_t sa = (uint32_t)__cvta_generic_to_shared(&As[s][ldRow][ldChunk]);
        cp_async16(sa, A + (size_t)(rowT + ldRow) * K + kt + ldChunk);
        uint32_t sb = (uint32_t)__cvta_generic_to_shared(&Bs[s][ldRow][ldChunk]);
        cp_async16(sb, BT + (size_t)(colT + ldRow) * K + kt + ldChunk);
    };

    load_stage(0, 0);
    cp_commit();
    load_stage(1, 16);
    cp_commit();

    for (int it = 0; it < iters; it++) {
        if (it + 1 < iters) asm volatile("cp.async.wait_group 1;");
        else                asm volatile("cp.async.wait_group 0;");
        __syncthreads();

        if (it + 2 < iters) {
            load_stage((it + 2) % 3, (it + 2) << 4);
            cp_commit();
        }

        int cur = it % 3;
        uint32_t af[2][4];
#pragma unroll
        for (int i = 0; i < 2; i++) {
            int m0 = wm + i * 16 + gr;
            af[i][0] = *reinterpret_cast<const uint32_t*>(&As[cur][m0][2 * tg]);
            af[i][1] = *reinterpret_cast<const uint32_t*>(&As[cur][m0 + 8][2 * tg]);
            af[i][2] = *reinterpret_cast<const uint32_t*>(&As[cur][m0][2 * tg + 8]);
            af[i][3] = *reinterpret_cast<const uint32_t*>(&As[cur][m0 + 8][2 * tg + 8]);
        }
        uint32_t bf[8][2];
#pragma unroll
        for (int j = 0; j < 8; j++) {
            int n0 = wn + j * 8 + gr;
            bf[j][0] = *reinterpret_cast<const uint32_t*>(&Bs[cur][n0][2 * tg]);
            bf[j][1] = *reinterpret_cast<const uint32_t*>(&Bs[cur][n0][2 * tg + 8]);
        }
#pragma unroll
        for (int i = 0; i < 2; i++)
#pragma unroll
            for (int j = 0; j < 8; j++) {
                asm volatile(
                    "mma.sync.aligned.m16n8k16.row.col.f32.f16.f16.f32 "
                    "{%0,%1,%2,%3},{%4,%5,%6,%7},{%8,%9},{%0,%1,%2,%3};"
                    : "+f"(acc[i][j][0]), "+f"(acc[i][j][1]),
                      "+f"(acc[i][j][2]), "+f"(acc[i][j][3])
                    : "r"(af[i][0]), "r"(af[i][1]), "r"(af[i][2]), "r"(af[i][3]),
                      "r"(bf[j][0]), "r"(bf[j][1]));
            }
        __syncthreads();
    }

    // store C (fp16)
#pragma unroll
    for (int i = 0; i < 2; i++) {
        int r0 = rowT + wm + i * 16 + gr;
#pragma unroll
        for (int j = 0; j < 8; j++) {
            int ccol = colT + wn + j * 8 + tg * 2;
            *reinterpret_cast<__half2*>(C + (size_t)r0 * Nc + ccol) =
                __floats2half2_rn(acc[i][j][0], acc[i][j][1]);
            *reinterpret_cast<__half2*>(C + (size_t)(r0 + 8) * Nc + ccol) =
                __floats2half2_rn(acc[i][j][2], acc[i][j][3]);
        }
    }

    // fused attention projections (z==0 only): partial el/er for this block's columns
    if (blockIdx.z == 0) {
        int d = Nc >> 1;
        int head = (colT + wn) >= d ? 1 : 0;   // block-warp columns never straddle heads
#pragma unroll
        for (int i = 0; i < 2; i++) {
            float pel0 = 0.f, per0 = 0.f, pel8 = 0.f, per8 = 0.f;
#pragma unroll
            for (int j = 0; j < 8; j++) {
                int ccol = colT + wn + j * 8 + tg * 2;
                float a0 = al[ccol], a1 = al[ccol + 1];
                float b0 = ar[ccol], b1 = ar[ccol + 1];
                pel0 = fmaf(acc[i][j][0], a0, fmaf(acc[i][j][1], a1, pel0));
                per0 = fmaf(acc[i][j][0], b0, fmaf(acc[i][j][1], b1, per0));
                pel8 = fmaf(acc[i][j][2], a0, fmaf(acc[i][j][3], a1, pel8));
                per8 = fmaf(acc[i][j][2], b0, fmaf(acc[i][j][3], b1, per8));
            }
            // reduce over tg quad (lanes xor 1, 2)
#pragma unroll
            for (int o = 1; o <= 2; o <<= 1) {
                pel0 += __shfl_xor_sync(0xffffffffu, pel0, o);
                per0 += __shfl_xor_sync(0xffffffffu, per0, o);
                pel8 += __shfl_xor_sync(0xffffffffu, pel8, o);
                per8 += __shfl_xor_sync(0xffffffffu, per8, o);
            }
            if (tg == 0) {
                int r0 = rowT + wm + i * 16 + gr;
                atomicAdd(&g_el[r0 * 2 + head], pel0);
                atomicAdd(&g_er[r0 * 2 + head], per0);
                atomicAdd(&g_el[(r0 + 8) * 2 + head], pel8);
                atomicAdd(&g_er[(r0 + 8) * 2 + head], per8);
            }
        }
    }
}

// ---------------- per-dst softmax + fp16 gather aggregation (+ fp16 residual) ---------
__global__ void __launch_bounds__(256) k_agg(int d) {
    const int HD = 2 * d;
    int n = blockIdx.x;
    int tid = threadIdx.x;
    int start = g_indptr[n];
    int deg = g_indptr[n + 1] - start;
    __shared__ float s_m0, s_m1, s_i0, s_i1;
    __shared__ int s_src[32];
    __shared__ float s_w[32][2];
    float er0 = g_er[n * 2 + 0];
    float er1 = g_er[n * 2 + 1];

    if (tid < 32) {
        float m0 = -1e30f, m1 = -1e30f;
        for (int j = tid; j < deg; j += 32) {
            int s = g_esrc[start + j];
            float e0 = lrelu(g_el[s * 2 + 0] + er0, 0.2f);
            float e1 = lrelu(g_el[s * 2 + 1] + er1, 0.2f);
            m0 = fmaxf(m0, e0); m1 = fmaxf(m1, e1);
        }
#pragma unroll
        for (int o = 16; o > 0; o >>= 1) {
            m0 = fmaxf(m0, __shfl_xor_sync(0xffffffffu, m0, o));
            m1 = fmaxf(m1, __shfl_xor_sync(0xffffffffu, m1, o));
        }
        float z0 = 0.f, z1 = 0.f;
        for (int j = tid; j < deg; j += 32) {
            int s = g_esrc[start + j];
            float e0 = lrelu(g_el[s * 2 + 0] + er0, 0.2f);
            float e1 = lrelu(g_el[s * 2 + 1] + er1, 0.2f);
            z0 += expf(e0 - m0);
            z1 += expf(e1 - m1);
        }
#pragma unroll
        for (int o = 16; o > 0; o >>= 1) {
            z0 += __shfl_xor_sync(0xffffffffu, z0, o);
            z1 += __shfl_xor_sync(0xffffffffu, z1, o);
        }
        if (tid == 0) {
            s_m0 = m0; s_m1 = m1;
            s_i0 = (deg > 0) ? 1.f / z0 : 0.f;
            s_i1 = (deg > 0) ? 1.f / z1 : 0.f;
        }
    }
    __syncthreads();
    float m0 = s_m0, m1 = s_m1, i0 = s_i0, i1 = s_i1;

    int dh = d >> 1;  // pairs in head 0 (d pairs total per row)
    float2 acc2[2];
    acc2[0] = make_float2(0.f, 0.f);
    acc2[1] = make_float2(0.f, 0.f);

    for (int c0 = 0; c0 < deg; c0 += 32) {
        int cn = min(32, deg - c0);
        if (tid < cn) {
            int s = g_esrc[start + c0 + tid];
            s_src[tid] = s;
            float e0 = lrelu(g_el[s * 2 + 0] + er0, 0.2f);
            float e1 = lrelu(g_el[s * 2 + 1] + er1, 0.2f);
            s_w[tid][0] = expf(e0 - m0) * i0;
            s_w[tid][1] = expf(e1 - m1) * i1;
        }
        __syncthreads();
        for (int j = 0; j < cn; j++) {
            const __half2* hrow = (const __half2*)(g_h + (size_t)s_src[j] * HD);
            float w0 = s_w[j][0], w1 = s_w[j][1];
#pragma unroll
            for (int k = 0; k < 2; k++) {
                int p = tid + k * 256;
                if (p < d) {
                    float w = (p < dh) ? w0 : w1;
                    float2 v = __half22float2(__ldg(hrow + p));
                    acc2[k].x = fmaf(w, v.x, acc2[k].x);
                    acc2[k].y = fmaf(w, v.y, acc2[k].y);
                }
            }
        }
        __syncthreads();
    }
#pragma unroll
    for (int k = 0; k < 2; k++) {
        int p = tid + k * 256;
        if (p < d) {
            float2 r = __half22float2(((const __half2*)g_r)[(size_t)n * d + p]);
            ((__half2*)g_x)[(size_t)n * d + p] =
                __floats2half2_rn(acc2[k].x + r.x, acc2[k].y + r.y);
        }
    }
}

// ---------------- GraphNorm stats (fp16 x, pair-wise) ----------------
__global__ void __launch_bounds__(256) k_colstats(int d) {
    int r0 = blockIdx.x * 32;
    int p = threadIdx.x;
    int q = d >> 1;
    if (p >= q) return;
    float a0 = 0.f, b0 = 0.f, a1 = 0.f, b1 = 0.f;
    for (int r = 0; r < 32; r++) {
        const __half2* row = (const __half2*)g_x + (size_t)(r0 + r) * q;
        float2 v = __half22float2(row[p]);
        a0 += v.x; b0 += v.x * v.x;
        a1 += v.y; b1 += v.y * v.y;
    }
    int c = p * 2;
    atomicAdd(&g_s1[c + 0], a0); atomicAdd(&g_s2[c + 0], b0);
    atomicAdd(&g_s1[c + 1], a1); atomicAdd(&g_s2[c + 1], b1);
}

// ---------------- normalize + lrelu + head-mean partials (finstats fused) -------------
__global__ void k_norm(const int* __restrict__ gid, const float* __restrict__ gamma,
                       const float* __restrict__ beta, const float* __restrict__ alpha,
                       int d, int off, int writeY) {
    int nb = blockIdx.x * 16;
    int g = gid[nb];
    int tid = threadIdx.x;
    const float inv_nh = 1.f / (float)(NN * HH);
    float2 sc[2], bi[2], acc[2];
    int w[2], act[2];
#pragma unroll
    for (int k = 0; k < 2; k++) {
        int p = tid + k * 256;
        act[k] = (p < d);
        acc[k] = make_float2(0.f, 0.f);
        if (act[k]) {
            int ch = 2 * p;
            int ww = (ch < d) ? ch : ch - d;
            w[k] = ww;
#pragma unroll
            for (int u = 0; u < 2; u++) {
                int c = ww + u;
                float mean = g_s1[c] * inv_nh;
                float ex2 = g_s2[c] * inv_nh;
                float a = alpha[c];
                float var = ex2 - 2.f * a * mean * mean + a * a * mean * mean;
                float s = gamma[c] * rsqrtf(var + 1e-5f);
                float b = beta[c] - s * a * mean;
                if (u == 0) { sc[k].x = s; bi[k].x = b; }
                else        { sc[k].y = s; bi[k].y = b; }
            }
        }
    }
    for (int i = 0; i < 16; i++) {
        size_t base2 = (size_t)(nb + i) * d;
        const __half2* xr = (const __half2*)g_x + base2;
        __half2* yr = (__half2*)g_abf + base2;
#pragma unroll
        for (int k = 0; k < 2; k++) {
            int p = tid + k * 256;
            if (act[k]) {
                float2 v = __half22float2(xr[p]);
                float y0 = lrelu(v.x * sc[k].x + bi[k].x, 0.01f);
                float y1 = lrelu(v.y * sc[k].y + bi[k].y, 0.01f);
                if (writeY) yr[p] = __floats2half2_rn(y0, y1);
                acc[k].x += y0;
                acc[k].y += y1;
            }
        }
    }
#pragma unroll
    for (int k = 0; k < 2; k++) {
        if (act[k]) {
            atomicAdd(&g_parts[g * OUTC + off + w[k] + 0], acc[k].x);
            atomicAdd(&g_parts[g * OUTC + off + w[k] + 1], acc[k].y);
        }
    }
}

// ---------------- final ----------------
__global__ void k_final(float* __restrict__ out) {
    int i = blockIdx.x * blockDim.x + threadIdx.x;
    if (i < BB * OUTC) {
        int b = i / OUTC;
        float v = g_parts[i] / (2.f * (float)g_counts[b]);
        out[i] = lrelu(v, 0.01f);
    }
}

// ---------------- launch ----------------
extern "C" void kernel_launch(void* const* d_in, const int* in_sizes, int n_in,
                              void* d_out, int out_size) {
    const float* nf = (const float*)d_in[0];
    const float* W[3]  = {(const float*)d_in[1],  (const float*)d_in[8],  (const float*)d_in[15]};
    const float* AL[3] = {(const float*)d_in[2],  (const float*)d_in[9],  (const float*)d_in[16]};
    const float* AR[3] = {(const float*)d_in[3],  (const float*)d_in[10], (const float*)d_in[17]};
    const float* RW[3] = {(const float*)d_in[4],  (const float*)d_in[11], (const float*)d_in[18]};
    const float* GA[3] = {(const float*)d_in[5],  (const float*)d_in[12], (const float*)d_in[19]};
    const float* BE[3] = {(const float*)d_in[6],  (const float*)d_in[13], (const float*)d_in[20]};
    const float* AP[3] = {(const float*)d_in[7],  (const float*)d_in[14], (const float*)d_in[21]};
    const int* src = (const int*)d_in[22];
    const int* dst = (const int*)d_in[23];
    const int* gid = (const int*)d_in[24];
    float* out = (float*)d_out;

    const int dims[3] = {128, 256, 512};
    const int offs[3] = {0, 128, 384};

    k_zero<<<(NN + 255) / 256, 256>>>();
    k_build<<<EE / 256, 256>>>(dst, gid);
    k_scan1<<<64, 256>>>();
    k_scan2<<<1, 64>>>();
    k_scan3<<<NN / 256, 256>>>();

    k_cvtA<<<(NN * 128 / 4 + 255) / 256, 256>>>(nf, NN * 128 / 4);
    {
        dim3 tg(32, 8);
        dim3 wg(dims[0] * 2 / 32, dims[0] / 32, 2);
        k_cvtW<<<wg, tg>>>(W[0], RW[0], dims[0], dims[0] * 2);
        dim3 gg(dims[0] * 2 / 128, NN / 128, 2);
        k_mma<<<gg, 256>>>(AL[0], AR[0], dims[0], dims[0] * 2);
    }
    k_scatter<<<EE / 256, 256>>>(src, dst);

    for (int l = 0; l < 3; l++) {
        int d = dims[l], HD = 2 * d;
        if (l > 0) {
            dim3 tg(32, 8);
            dim3 wg(HD / 32, d / 32, 2);
            k_cvtW<<<wg, tg>>>(W[l], RW[l], d, HD);
            dim3 gg(HD / 128, NN / 128, 2);
            k_mma<<<gg, 256>>>(AL[l], AR[l], d, HD);
        }
        k_agg<<<NN, 256>>>(d);
        k_colstats<<<(NN * HH) / 32, 256>>>(d);
        k_norm<<<NN / 16, 256>>>(gid, GA[l], BE[l], AP[l], d, offs[l], (l < 2) ? 1 : 0);
    }
    k_final<<<(BB * OUTC + 255) / 256, 256>>>(out);
}

// round 17
// speedup vs baseline: 1.4602x; 1.0050x over previous
#include <cuda_runtime.h>
#include <cuda_fp16.h>
#include <math.h>
#include <stdint.h>

#define NN 16384
#define EE 131072
#define BB 16
#define HH 2
#define MAXD 512
#define MAXHD 1024
#define OUTC 896

// ---------------- scratch (device globals; no allocation) ----------------
__device__ __half g_x[(size_t)NN * MAXHD];       // fp16 GAT output (agg result)
__device__ __half g_abf[(size_t)NN * MAXD];      // fp16 GEMM input (A)
__device__ __half g_wTa[(size_t)MAXD * MAXHD];   // fp16 W transposed [N][K]
__device__ __half g_wTb[(size_t)MAXD * MAXHD];   // fp16 rW transposed [N][K]
__device__ __half g_h[(size_t)NN * MAXHD];       // fp16 h = x @ W
__device__ __half g_r[(size_t)NN * MAXHD];       // fp16 residual
__device__ float g_el[NN * HH];
__device__ float g_er[NN * HH];
__device__ int   g_indptr[NN + 1];
__device__ int   g_cnt[NN];
__device__ int   g_cur[NN];
__device__ int   g_esrc[EE];
__device__ int   g_bsum[64];
__device__ int   g_boff[64];
__device__ float g_s1[MAXD];
__device__ float g_s2[MAXD];
__device__ float g_parts[BB * OUTC];
__device__ int   g_counts[BB];

__device__ __forceinline__ float lrelu(float v, float s) { return v > 0.f ? v : s * v; }

__device__ __forceinline__ void cp_async16(uint32_t saddr, const void* gptr) {
    asm volatile("cp.async.cg.shared.global [%0], [%1], 16;" :: "r"(saddr), "l"(gptr));
}
__device__ __forceinline__ void cp_commit() { asm volatile("cp.async.commit_group;"); }

// ---------------- front ----------------
__global__ void k_zero() {
    int i = blockIdx.x * blockDim.x + threadIdx.x;
    if (i < BB * OUTC) g_parts[i] = 0.f;
    if (i < BB) g_counts[i] = 0;
    if (i < NN) g_cnt[i] = 0;
}

__global__ void k_build(const int* __restrict__ dst, const int* __restrict__ gid) {
    int i = blockIdx.x * blockDim.x + threadIdx.x;
    if (i < EE) atomicAdd(&g_cnt[dst[i]], 1);
    if (i < NN) atomicAdd(&g_counts[gid[i]], 1);
}

__global__ void k_scan1() {
    __shared__ int sm[256];
    int tid = threadIdx.x;
    int i = blockIdx.x * 256 + tid;
    int v = g_cnt[i];
    sm[tid] = v;
    __syncthreads();
    for (int off = 1; off < 256; off <<= 1) {
        int t = (tid >= off) ? sm[tid - off] : 0;
        __syncthreads();
        sm[tid] += t;
        __syncthreads();
    }
    g_indptr[i] = sm[tid] - v;
    g_cur[i] = 0;
    if (tid == 255) g_bsum[blockIdx.x] = sm[255];
}

__global__ void k_scan2() {
    __shared__ int sm[64];
    int tid = threadIdx.x;
    int v = g_bsum[tid];
    sm[tid] = v;
    __syncthreads();
    for (int off = 1; off < 64; off <<= 1) {
        int t = (tid >= off) ? sm[tid - off] : 0;
        __syncthreads();
        sm[tid] += t;
        __syncthreads();
    }
    g_boff[tid] = sm[tid] - v;
    if (tid == 63) g_indptr[NN] = sm[63];
}

__global__ void k_scan3() {
    int i = blockIdx.x * blockDim.x + threadIdx.x;
    if (i < NN) g_indptr[i] += g_boff[i >> 8];
}

__global__ void k_scatter(const int* __restrict__ src, const int* __restrict__ dst) {
    int i = blockIdx.x * blockDim.x + threadIdx.x;
    if (i < EE) {
        int d = dst[i];
        int p = g_indptr[d] + atomicAdd(&g_cur[d], 1);
        g_esrc[p] = src[i];
    }
}

// ---------------- fp32 -> fp16 conversions ----------------
__global__ void k_cvtA(const float* __restrict__ src, int n4) {
    int i = blockIdx.x * blockDim.x + threadIdx.x;
    if (i < n4) {
        float4 v = reinterpret_cast<const float4*>(src)[i];
        __half2* o = reinterpret_cast<__half2*>(g_abf);
        o[2 * i + 0] = __floats2half2_rn(v.x, v.y);
        o[2 * i + 1] = __floats2half2_rn(v.z, v.w);
    }
}

// transpose+convert AND zero per-layer accumulators (el/er/s1/s2)
__global__ void k_cvtW(const float* __restrict__ W, const float* __restrict__ R,
                       int K, int N) {
    int total = gridDim.x * gridDim.y * gridDim.z * 256;
    int lin = (((blockIdx.z * gridDim.y + blockIdx.y) * gridDim.x + blockIdx.x) * 256)
              + threadIdx.y * 32 + threadIdx.x;
    for (int t = lin; t < NN * HH; t += total) { g_el[t] = 0.f; g_er[t] = 0.f; }
    if (lin < MAXD) { g_s1[lin] = 0.f; g_s2[lin] = 0.f; }

    __shared__ float tbuf[32][33];
    const float* S = blockIdx.z ? R : W;
    __half* D = blockIdx.z ? g_wTb : g_wTa;
    int n0 = blockIdx.x * 32, k0 = blockIdx.y * 32;
    for (int r = threadIdx.y; r < 32; r += 8)
        tbuf[r][threadIdx.x] = S[(size_t)(k0 + r) * N + n0 + threadIdx.x];
    __syncthreads();
    for (int r = threadIdx.y; r < 32; r += 8)
        D[(size_t)(n0 + r) * K + k0 + threadIdx.x] = __float2half(tbuf[threadIdx.x][r]);
}

// ---------------- FP16 tensor-core GEMM (m16n8k16) + fused attn projections ----------
// Block 128x128, BK=32, 2-stage cp.async. z=0: C=g_h + el/er; z=1: C=g_r.
__global__ void __launch_bounds__(256) k_mma(const float* __restrict__ al,
                                             const float* __restrict__ ar,
                                             int K, int Nc) {
    __shared__ __align__(16) __half As[2][128][40];
    __shared__ __align__(16) __half Bs[2][128][40];

    const __half* A = g_abf;
    const __half* BT = blockIdx.z ? g_wTb : g_wTa;
    __half* C = blockIdx.z ? g_r : g_h;

    int tid = threadIdx.x;
    int lane = tid & 31;
    int warp = tid >> 5;
    int wm = (warp >> 1) * 32;
    int wn = (warp & 1) * 64;
    int rowT = blockIdx.y * 128;
    int colT = blockIdx.x * 128;
    int gr = lane >> 2;
    int tg = lane & 3;

    int ldRow = tid >> 1;
    int ldChunk = (tid & 1) * 8;

    float acc[2][8][4];
#pragma unroll
    for (int i = 0; i < 2; i++)
#pragma unroll
        for (int j = 0; j < 8; j++)
#pragma unroll
            for (int c = 0; c < 4; c++) acc[i][j][c] = 0.f;

    int iters = K >> 5;   // BK=32; K in {128,256,512} -> 4/8/16

    auto load_stage = [&](int s, int kt) {
        uint32_t sa = (uint32_t)__cvta_generic_to_shared(&As[s][ldRow][ldChunk]);
        cp_async16(sa, A + (size_t)(rowT + ldRow) * K + kt + ldChunk);
        uint32_t sa2 = (uint32_t)__cvta_generic_to_shared(&As[s][ldRow][ldChunk + 16]);
        cp_async16(sa2, A + (size_t)(rowT + ldRow) * K + kt + ldChunk + 16);
        uint32_t sb = (uint32_t)__cvta_generic_to_shared(&Bs[s][ldRow][ldChunk]);
        cp_async16(sb, BT + (size_t)(colT + ldRow) * K + kt + ldChunk);
        uint32_t sb2 = (uint32_t)__cvta_generic_to_shared(&Bs[s][ldRow][ldChunk + 16]);
        cp_async16(sb2, BT + (size_t)(colT + ldRow) * K + kt + ldChunk + 16);
    };

    load_stage(0, 0);
    cp_commit();

    for (int it = 0; it < iters; it++) {
        if (it + 1 < iters) {
            load_stage((it + 1) & 1, (it + 1) << 5);
            cp_commit();
            asm volatile("cp.async.wait_group 1;");
        } else {
            asm volatile("cp.async.wait_group 0;");
        }
        __syncthreads();

        int cur = it & 1;
#pragma unroll
        for (int kk = 0; kk < 32; kk += 16) {
            uint32_t af[2][4];
#pragma unroll
            for (int i = 0; i < 2; i++) {
                int m0 = wm + i * 16 + gr;
                af[i][0] = *reinterpret_cast<const uint32_t*>(&As[cur][m0][kk + 2 * tg]);
                af[i][1] = *reinterpret_cast<const uint32_t*>(&As[cur][m0 + 8][kk + 2 * tg]);
                af[i][2] = *reinterpret_cast<const uint32_t*>(&As[cur][m0][kk + 2 * tg + 8]);
                af[i][3] = *reinterpret_cast<const uint32_t*>(&As[cur][m0 + 8][kk + 2 * tg + 8]);
            }
            uint32_t bf[8][2];
#pragma unroll
            for (int j = 0; j < 8; j++) {
                int n0 = wn + j * 8 + gr;
                bf[j][0] = *reinterpret_cast<const uint32_t*>(&Bs[cur][n0][kk + 2 * tg]);
                bf[j][1] = *reinterpret_cast<const uint32_t*>(&Bs[cur][n0][kk + 2 * tg + 8]);
            }
#pragma unroll
            for (int i = 0; i < 2; i++)
#pragma unroll
                for (int j = 0; j < 8; j++) {
                    asm volatile(
                        "mma.sync.aligned.m16n8k16.row.col.f32.f16.f16.f32 "
                        "{%0,%1,%2,%3},{%4,%5,%6,%7},{%8,%9},{%0,%1,%2,%3};"
                        : "+f"(acc[i][j][0]), "+f"(acc[i][j][1]),
                          "+f"(acc[i][j][2]), "+f"(acc[i][j][3])
                        : "r"(af[i][0]), "r"(af[i][1]), "r"(af[i][2]), "r"(af[i][3]),
                          "r"(bf[j][0]), "r"(bf[j][1]));
                }
        }
        __syncthreads();
    }

    // store C (fp16)
#pragma unroll
    for (int i = 0; i < 2; i++) {
        int r0 = rowT + wm + i * 16 + gr;
#pragma unroll
        for (int j = 0; j < 8; j++) {
            int ccol = colT + wn + j * 8 + tg * 2;
            *reinterpret_cast<__half2*>(C + (size_t)r0 * Nc + ccol) =
                __floats2half2_rn(acc[i][j][0], acc[i][j][1]);
            *reinterpret_cast<__half2*>(C + (size_t)(r0 + 8) * Nc + ccol) =
                __floats2half2_rn(acc[i][j][2], acc[i][j][3]);
        }
    }

    // fused attention projections (z==0 only)
    if (blockIdx.z == 0) {
        int d = Nc >> 1;
        int head = (colT + wn) >= d ? 1 : 0;
#pragma unroll
        for (int i = 0; i < 2; i++) {
            float pel0 = 0.f, per0 = 0.f, pel8 = 0.f, per8 = 0.f;
#pragma unroll
            for (int j = 0; j < 8; j++) {
                int ccol = colT + wn + j * 8 + tg * 2;
                float a0 = al[ccol], a1 = al[ccol + 1];
                float b0 = ar[ccol], b1 = ar[ccol + 1];
                pel0 = fmaf(acc[i][j][0], a0, fmaf(acc[i][j][1], a1, pel0));
                per0 = fmaf(acc[i][j][0], b0, fmaf(acc[i][j][1], b1, per0));
                pel8 = fmaf(acc[i][j][2], a0, fmaf(acc[i][j][3], a1, pel8));
                per8 = fmaf(acc[i][j][2], b0, fmaf(acc[i][j][3], b1, per8));
            }
#pragma unroll
            for (int o = 1; o <= 2; o <<= 1) {
                pel0 += __shfl_xor_sync(0xffffffffu, pel0, o);
                per0 += __shfl_xor_sync(0xffffffffu, per0, o);
                pel8 += __shfl_xor_sync(0xffffffffu, pel8, o);
                per8 += __shfl_xor_sync(0xffffffffu, per8, o);
            }
            if (tg == 0) {
                int r0 = rowT + wm + i * 16 + gr;
                atomicAdd(&g_el[r0 * 2 + head], pel0);
                atomicAdd(&g_er[r0 * 2 + head], per0);
                atomicAdd(&g_el[(r0 + 8) * 2 + head], pel8);
                atomicAdd(&g_er[(r0 + 8) * 2 + head], per8);
            }
        }
    }
}

// ---------------- per-dst softmax + fp16 gather aggregation (+ fp16 residual) ---------
__global__ void __launch_bounds__(256) k_agg(int d) {
    const int HD = 2 * d;
    int n = blockIdx.x;
    int tid = threadIdx.x;
    int start = g_indptr[n];
    int deg = g_indptr[n + 1] - start;
    __shared__ float s_m0, s_m1, s_i0, s_i1;
    __shared__ int s_src[32];
    __shared__ float s_w[32][2];
    float er0 = g_er[n * 2 + 0];
    float er1 = g_er[n * 2 + 1];

    if (tid < 32) {
        float m0 = -1e30f, m1 = -1e30f;
        for (int j = tid; j < deg; j += 32) {
            int s = g_esrc[start + j];
            float e0 = lrelu(g_el[s * 2 + 0] + er0, 0.2f);
            float e1 = lrelu(g_el[s * 2 + 1] + er1, 0.2f);
            m0 = fmaxf(m0, e0); m1 = fmaxf(m1, e1);
        }
#pragma unroll
        for (int o = 16; o > 0; o >>= 1) {
            m0 = fmaxf(m0, __shfl_xor_sync(0xffffffffu, m0, o));
            m1 = fmaxf(m1, __shfl_xor_sync(0xffffffffu, m1, o));
        }
        float z0 = 0.f, z1 = 0.f;
        for (int j = tid; j < deg; j += 32) {
            int s = g_esrc[start + j];
            float e0 = lrelu(g_el[s * 2 + 0] + er0, 0.2f);
            float e1 = lrelu(g_el[s * 2 + 1] + er1, 0.2f);
            z0 += expf(e0 - m0);
            z1 += expf(e1 - m1);
        }
#pragma unroll
        for (int o = 16; o > 0; o >>= 1) {
            z0 += __shfl_xor_sync(0xffffffffu, z0, o);
            z1 += __shfl_xor_sync(0xffffffffu, z1, o);
        }
        if (tid == 0) {
            s_m0 = m0; s_m1 = m1;
            s_i0 = (deg > 0) ? 1.f / z0 : 0.f;
            s_i1 = (deg > 0) ? 1.f / z1 : 0.f;
        }
    }
    __syncthreads();
    float m0 = s_m0, m1 = s_m1, i0 = s_i0, i1 = s_i1;

    int dh = d >> 1;
    float2 acc2[2];
    acc2[0] = make_float2(0.f, 0.f);
    acc2[1] = make_float2(0.f, 0.f);

    for (int c0 = 0; c0 < deg; c0 += 32) {
        int cn = min(32, deg - c0);
        if (tid < cn) {
            int s = g_esrc[start + c0 + tid];
            s_src[tid] = s;
            float e0 = lrelu(g_el[s * 2 + 0] + er0, 0.2f);
            float e1 = lrelu(g_el[s * 2 + 1] + er1, 0.2f);
            s_w[tid][0] = expf(e0 - m0) * i0;
            s_w[tid][1] = expf(e1 - m1) * i1;
        }
        __syncthreads();
        int j = 0;
        for (; j + 1 < cn; j += 2) {
            const __half2* h0 = (const __half2*)(g_h + (size_t)s_src[j] * HD);
            const __half2* h1 = (const __half2*)(g_h + (size_t)s_src[j + 1] * HD);
            float wa0 = s_w[j][0], wa1 = s_w[j][1];
            float wb0 = s_w[j + 1][0], wb1 = s_w[j + 1][1];
#pragma unroll
            for (int k = 0; k < 2; k++) {
                int p = tid + k * 256;
                if (p < d) {
                    float wa = (p < dh) ? wa0 : wa1;
                    float wb = (p < dh) ? wb0 : wb1;
                    float2 v0 = __half22float2(__ldg(h0 + p));
                    float2 v1 = __half22float2(__ldg(h1 + p));
                    acc2[k].x = fmaf(wa, v0.x, acc2[k].x);
                    acc2[k].y = fmaf(wa, v0.y, acc2[k].y);
                    acc2[k].x = fmaf(wb, v1.x, acc2[k].x);
                    acc2[k].y = fmaf(wb, v1.y, acc2[k].y);
                }
            }
        }
        if (j < cn) {
            const __half2* h0 = (const __half2*)(g_h + (size_t)s_src[j] * HD);
            float wa0 = s_w[j][0], wa1 = s_w[j][1];
#pragma unroll
            for (int k = 0; k < 2; k++) {
                int p = tid + k * 256;
                if (p < d) {
                    float wa = (p < dh) ? wa0 : wa1;
                    float2 v0 = __half22float2(__ldg(h0 + p));
                    acc2[k].x = fmaf(wa, v0.x, acc2[k].x);
                    acc2[k].y = fmaf(wa, v0.y, acc2[k].y);
                }
            }
        }
        __syncthreads();
    }
#pragma unroll
    for (int k = 0; k < 2; k++) {
        int p = tid + k * 256;
        if (p < d) {
            float2 r = __half22float2(((const __half2*)g_r)[(size_t)n * d + p]);
            ((__half2*)g_x)[(size_t)n * d + p] =
                __floats2half2_rn(acc2[k].x + r.x, acc2[k].y + r.y);
        }
    }
}

// ---------------- GraphNorm stats (fp16 x, pair-wise) ----------------
__global__ void __launch_bounds__(256) k_colstats(int d) {
    int r0 = blockIdx.x * 32;
    int p = threadIdx.x;
    int q = d >> 1;
    if (p >= q) return;
    float a0 = 0.f, b0 = 0.f, a1 = 0.f, b1 = 0.f;
    for (int r = 0; r < 32; r++) {
        const __half2* row = (const __half2*)g_x + (size_t)(r0 + r) * q;
        float2 v = __half22float2(row[p]);
        a0 += v.x; b0 += v.x * v.x;
        a1 += v.y; b1 += v.y * v.y;
    }
    int c = p * 2;
    atomicAdd(&g_s1[c + 0], a0); atomicAdd(&g_s2[c + 0], b0);
    atomicAdd(&g_s1[c + 1], a1); atomicAdd(&g_s2[c + 1], b1);
}

// ---------------- normalize + lrelu + head-mean partials (finstats fused) -------------
__global__ void k_norm(const int* __restrict__ gid, const float* __restrict__ gamma,
                       const float* __restrict__ beta, const float* __restrict__ alpha,
                       int d, int off, int writeY) {
    int nb = blockIdx.x * 16;
    int g = gid[nb];
    int tid = threadIdx.x;
    const float inv_nh = 1.f / (float)(NN * HH);
    float2 sc[2], bi[2], acc[2];
    int w[2], act[2];
#pragma unroll
    for (int k = 0; k < 2; k++) {
        int p = tid + k * 256;
        act[k] = (p < d);
        acc[k] = make_float2(0.f, 0.f);
        if (act[k]) {
            int ch = 2 * p;
            int ww = (ch < d) ? ch : ch - d;
            w[k] = ww;
#pragma unroll
            for (int u = 0; u < 2; u++) {
                int c = ww + u;
                float mean = g_s1[c] * inv_nh;
                float ex2 = g_s2[c] * inv_nh;
                float a = alpha[c];
                float var = ex2 - 2.f * a * mean * mean + a * a * mean * mean;
                float s = gamma[c] * rsqrtf(var + 1e-5f);
                float b = beta[c] - s * a * mean;
                if (u == 0) { sc[k].x = s; bi[k].x = b; }
                else        { sc[k].y = s; bi[k].y = b; }
            }
        }
    }
    for (int i = 0; i < 16; i++) {
        size_t base2 = (size_t)(nb + i) * d;
        const __half2* xr = (const __half2*)g_x + base2;
        __half2* yr = (__half2*)g_abf + base2;
#pragma unroll
        for (int k = 0; k < 2; k++) {
            int p = tid + k * 256;
            if (act[k]) {
                float2 v = __half22float2(xr[p]);
                float y0 = lrelu(v.x * sc[k].x + bi[k].x, 0.01f);
                float y1 = lrelu(v.y * sc[k].y + bi[k].y, 0.01f);
                if (writeY) yr[p] = __floats2half2_rn(y0, y1);
                acc[k].x += y0;
                acc[k].y += y1;
            }
        }
    }
#pragma unroll
    for (int k = 0; k < 2; k++) {
        if (act[k]) {
            atomicAdd(&g_parts[g * OUTC + off + w[k] + 0], acc[k].x);
            atomicAdd(&g_parts[g * OUTC + off + w[k] + 1], acc[k].y);
        }
    }
}

// ---------------- final ----------------
__global__ void k_final(float* __restrict__ out) {
    int i = blockIdx.x * blockDim.x + threadIdx.x;
    if (i < BB * OUTC) {
        int b = i / OUTC;
        float v = g_parts[i] / (2.f * (float)g_counts[b]);
        out[i] = lrelu(v, 0.01f);
    }
}

// ---------------- launch ----------------
extern "C" void kernel_launch(void* const* d_in, const int* in_sizes, int n_in,
                              void* d_out, int out_size) {
    const float* nf = (const float*)d_in[0];
    const float* W[3]  = {(const float*)d_in[1],  (const float*)d_in[8],  (const float*)d_in[15]};
    const float* AL[3] = {(const float*)d_in[2],  (const float*)d_in[9],  (const float*)d_in[16]};
    const float* AR[3] = {(const float*)d_in[3],  (const float*)d_in[10], (const float*)d_in[17]};
    const float* RW[3] = {(const float*)d_in[4],  (const float*)d_in[11], (const float*)d_in[18]};
    const float* GA[3] = {(const float*)d_in[5],  (const float*)d_in[12], (const float*)d_in[19]};
    const float* BE[3] = {(const float*)d_in[6],  (const float*)d_in[13], (const float*)d_in[20]};
    const float* AP[3] = {(const float*)d_in[7],  (const float*)d_in[14], (const float*)d_in[21]};
    const int* src = (const int*)d_in[22];
    const int* dst = (const int*)d_in[23];
    const int* gid = (const int*)d_in[24];
    float* out = (float*)d_out;

    const int dims[3] = {128, 256, 512};
    const int offs[3] = {0, 128, 384};

    k_zero<<<(NN + 255) / 256, 256>>>();
    k_build<<<EE / 256, 256>>>(dst, gid);
    k_scan1<<<64, 256>>>();
    k_scan2<<<1, 64>>>();
    k_scan3<<<NN / 256, 256>>>();

    k_cvtA<<<(NN * 128 / 4 + 255) / 256, 256>>>(nf, NN * 128 / 4);
    {
        dim3 tg(32, 8);
        dim3 wg(dims[0] * 2 / 32, dims[0] / 32, 2);
        k_cvtW<<<wg, tg>>>(W[0], RW[0], dims[0], dims[0] * 2);
        dim3 gg(dims[0] * 2 / 128, NN / 128, 2);
        k_mma<<<gg, 256>>>(AL[0], AR[0], dims[0], dims[0] * 2);
    }
    k_scatter<<<EE / 256, 256>>>(src, dst);

    for (int l = 0; l < 3; l++) {
        int d = dims[l], HD = 2 * d;
        if (l > 0) {
            dim3 tg(32, 8);
            dim3 wg(HD / 32, d / 32, 2);
            k_cvtW<<<wg, tg>>>(W[l], RW[l], d, HD);
            dim3 gg(HD / 128, NN / 128, 2);
            k_mma<<<gg, 256>>>(AL[l], AR[l], d, HD);
        }
        k_agg<<<NN, 256>>>(d);
        k_colstats<<<(NN * HH) / 32, 256>>>(d);
        k_norm<<<NN / 16, 256>>>(gid, GA[l], BE[l], AP[l], d, offs[l], (l < 2) ? 1 : 0);
    }
    k_final<<<(BB * OUTC + 255) / 256, 256>>>(out);
}